// round 8
// baseline (speedup 1.0000x reference)
#include <cuda_runtime.h>
#include <cuda_bf16.h>
#include <cuda_fp16.h>
#include <math_constants.h>
#include <cstdint>

#define N_NODES 50000
#define N_EDGES 800000
#define HID 128
#define PW 384   // [0:128)=z@Ws, [128:256)=z@Wd, [256:384)=z@W1a
#define SCAN_BLOCKS ((N_NODES + 255) / 256)   // 196

// ---------------- scratch ----------------
__device__ float  g_P[(size_t)N_NODES * PW];
__device__ __half g_Ps16[(size_t)N_NODES * HID];   // fp16 copy of z@Ws for edge gather
__device__ float  g_agg[(size_t)N_NODES * HID];
__device__ float  g_hidden[(size_t)N_NODES * HID];
__device__ int    g_count[N_NODES];
__device__ int    g_offset[N_NODES];
__device__ int    g_cursor[N_NODES];
__device__ int    g_blocksum[SCAN_BLOCKS];
__device__ int2   g_sorted[N_EDGES];               // (src, w bits)

// ---------------- mma.sync helpers (portable sm_80+ PTX) ----------------
__device__ __forceinline__ uint32_t smem_u32(const void* p) {
    uint32_t a;
    asm("{ .reg .u64 t; cvta.to.shared.u64 t, %1; cvt.u32.u64 %0, t; }" : "=r"(a) : "l"(p));
    return a;
}
__device__ __forceinline__ void ldsm_x4(uint32_t* r, uint32_t addr) {
    asm volatile("ldmatrix.sync.aligned.m8n8.x4.shared.b16 {%0,%1,%2,%3}, [%4];"
                 : "=r"(r[0]), "=r"(r[1]), "=r"(r[2]), "=r"(r[3]) : "r"(addr));
}
__device__ __forceinline__ void ldsm_x4_t(uint32_t* r, uint32_t addr) {
    asm volatile("ldmatrix.sync.aligned.m8n8.x4.trans.shared.b16 {%0,%1,%2,%3}, [%4];"
                 : "=r"(r[0]), "=r"(r[1]), "=r"(r[2]), "=r"(r[3]) : "r"(addr));
}
__device__ __forceinline__ void mma16816(float* c, const uint32_t* a, const uint32_t* b) {
    asm volatile(
        "mma.sync.aligned.m16n8k16.row.col.f32.bf16.bf16.f32 "
        "{%0,%1,%2,%3}, {%4,%5,%6,%7}, {%8,%9}, {%0,%1,%2,%3};"
        : "+f"(c[0]), "+f"(c[1]), "+f"(c[2]), "+f"(c[3])
        : "r"(a[0]), "r"(a[1]), "r"(a[2]), "r"(a[3]), "r"(b[0]), "r"(b[1]));
}
__device__ __forceinline__ uint32_t pack2(float x, float y) {
    __nv_bfloat162 h = __floats2bfloat162_rn(x, y);
    return *(uint32_t*)&h;
}
// swizzled byte offset inside a [128][128] bf16 tile (256B rows)
__device__ __forceinline__ uint32_t swz(int row, int col) {
    return (uint32_t)(row * 256 + ((((col >> 3) ^ (row & 7))) << 4) + (col & 7) * 2);
}

// smem plan (dynamic, 128 KB)
#define SM_AHI 0
#define SM_ALO 32768
#define SM_BHI 65536
#define SM_BLO 98304
#define SM_TOTAL 131072

// out[r][ocol0 + c] = f(A_tile @ B + bias + Cadd);  D = Ahi@Bhi + Ahi@Blo + Alo@Bhi
__global__ __launch_bounds__(256)
void mma_gemm(const float* __restrict__ A,
              const float* __restrict__ Bp0, const float* __restrict__ Bp1,
              const float* __restrict__ Bp2,
              const float* __restrict__ bias, const float* __restrict__ Cadd, int ldCadd,
              float* __restrict__ out, int ldOut, int M, int relu, int fp16tab)
{
    extern __shared__ char smem[];
    const uint32_t sb = smem_u32(smem);
    const int tid = threadIdx.x;
    const int wid = tid >> 5;
    const int lane = tid & 31;
    const int bm0 = blockIdx.x * 128;
    const int by = blockIdx.y;
    const float* B = (by == 0) ? Bp0 : ((by == 1) ? Bp1 : Bp2);
    const int ocol0 = by * 128;

    // ---- convert A tile: fp32 -> (hi, lo) bf16, swizzled smem ----
#pragma unroll
    for (int i = 0; i < 32; i++) {
        int p = tid + i * 256;
        int row = p >> 6;
        int col = (p & 63) * 2;
        float2 v = make_float2(0.f, 0.f);
        int gr = bm0 + row;
        if (gr < M) v = *(const float2*)(A + (size_t)gr * 128 + col);
        float hx = __bfloat162float(__float2bfloat16(v.x));
        float hy = __bfloat162float(__float2bfloat16(v.y));
        uint32_t off = swz(row, col);
        *(uint32_t*)(smem + SM_AHI + off) = pack2(hx, hy);
        *(uint32_t*)(smem + SM_ALO + off) = pack2(v.x - hx, v.y - hy);
    }
    // ---- convert B tile ----
#pragma unroll
    for (int i = 0; i < 32; i++) {
        int p = tid + i * 256;
        int row = p >> 6;
        int col = (p & 63) * 2;
        float2 v = *(const float2*)(B + (size_t)row * 128 + col);
        float hx = __bfloat162float(__float2bfloat16(v.x));
        float hy = __bfloat162float(__float2bfloat16(v.y));
        uint32_t off = swz(row, col);
        *(uint32_t*)(smem + SM_BHI + off) = pack2(hx, hy);
        *(uint32_t*)(smem + SM_BLO + off) = pack2(v.x - hx, v.y - hy);
    }
    __syncthreads();

    const int wm = wid & 1;
    const int wn = wid >> 1;
    const int sub = lane >> 3;
    const int l7 = lane & 7;
    const int radd = (sub & 1) * 8;
    const int cadd = (sub >> 1) * 8;

    float acc[4][4][4];
#pragma unroll
    for (int mt = 0; mt < 4; mt++)
#pragma unroll
        for (int nt = 0; nt < 4; nt++)
#pragma unroll
            for (int j = 0; j < 4; j++) acc[mt][nt][j] = 0.f;

#pragma unroll
    for (int ks = 0; ks < 8; ks++) {
        const int k0 = ks * 16;
        uint32_t aH[4][4], aL[4][4], bH[2][4], bL[2][4];
#pragma unroll
        for (int mt = 0; mt < 4; mt++) {
            uint32_t o = swz(wm * 64 + mt * 16 + l7 + radd, k0 + cadd);
            ldsm_x4(aH[mt], sb + SM_AHI + o);
            ldsm_x4(aL[mt], sb + SM_ALO + o);
        }
#pragma unroll
        for (int pr = 0; pr < 2; pr++) {
            uint32_t o = swz(k0 + l7 + radd, wn * 32 + pr * 16 + cadd);
            ldsm_x4_t(bH[pr], sb + SM_BHI + o);
            ldsm_x4_t(bL[pr], sb + SM_BLO + o);
        }
#pragma unroll
        for (int mt = 0; mt < 4; mt++)
#pragma unroll
            for (int nt = 0; nt < 4; nt++) {
                const uint32_t* bh = &bH[nt >> 1][(nt & 1) * 2];
                const uint32_t* bl = &bL[nt >> 1][(nt & 1) * 2];
                mma16816(acc[mt][nt], aH[mt], bh);
                mma16816(acc[mt][nt], aH[mt], bl);
                mma16816(acc[mt][nt], aL[mt], bh);
            }
    }

    // ---- epilogue ----
    const int g = lane >> 2;
    const int tg = lane & 3;
#pragma unroll
    for (int mt = 0; mt < 4; mt++) {
#pragma unroll
        for (int half = 0; half < 2; half++) {
            int r = bm0 + wm * 64 + mt * 16 + g + half * 8;
            if (r >= M) continue;
            float* orow = out + (size_t)r * ldOut + ocol0;
            const float* crow = Cadd ? (Cadd + (size_t)r * ldCadd) : nullptr;
#pragma unroll
            for (int nt = 0; nt < 4; nt++) {
                int lc = wn * 32 + nt * 8 + 2 * tg;
                float2 v;
                v.x = acc[mt][nt][half * 2 + 0];
                v.y = acc[mt][nt][half * 2 + 1];
                if (bias) { v.x += bias[lc]; v.y += bias[lc + 1]; }
                if (crow) { v.x += crow[lc]; v.y += crow[lc + 1]; }
                if (relu) { v.x = fmaxf(v.x, 0.f); v.y = fmaxf(v.y, 0.f); }
                *(float2*)(orow + lc) = v;
                if (fp16tab && by == 0) {
                    __half2 h = __floats2half2_rn(v.x, v.y);
                    *(__half2*)(g_Ps16 + (size_t)r * HID + lc) = h;
                }
            }
        }
    }
}

// ---------------- edge counting sort ----------------
__global__ void zero_count_kernel() {
    int i = blockIdx.x * blockDim.x + threadIdx.x;
    if (i < N_NODES) g_count[i] = 0;
}
__global__ void hist_kernel(const int* __restrict__ edst) {
    int i = blockIdx.x * blockDim.x + threadIdx.x;
    if (i < N_EDGES) atomicAdd(&g_count[edst[i]], 1);
}
__global__ void scan_local() {
    int b = blockIdx.x, t = threadIdx.x;
    int i = b * 256 + t;
    int v = (i < N_NODES) ? g_count[i] : 0;
    int lane = t & 31, w = t >> 5;
    int incl = v;
#pragma unroll
    for (int o = 1; o < 32; o <<= 1) {
        int y = __shfl_up_sync(0xffffffffu, incl, o);
        if (lane >= o) incl += y;
    }
    __shared__ int ws[8];
    if (lane == 31) ws[w] = incl;
    __syncthreads();
    if (t < 8) {
        int x = ws[t];
#pragma unroll
        for (int o = 1; o < 8; o <<= 1) {
            int y = __shfl_up_sync(0xffu, x, o, 8);
            if (t >= o) x += y;
        }
        ws[t] = x;
    }
    __syncthreads();
    int excl = incl - v + (w > 0 ? ws[w - 1] : 0);
    if (i < N_NODES) g_offset[i] = excl;
    if (t == 255) g_blocksum[b] = ws[7];
}
__global__ void scan_sums() {
    int t = threadIdx.x;
    int v = (t < SCAN_BLOCKS) ? g_blocksum[t] : 0;
    int lane = t & 31, w = t >> 5;
    int incl = v;
#pragma unroll
    for (int o = 1; o < 32; o <<= 1) {
        int y = __shfl_up_sync(0xffffffffu, incl, o);
        if (lane >= o) incl += y;
    }
    __shared__ int ws[8];
    if (lane == 31) ws[w] = incl;
    __syncthreads();
    if (t < 8) {
        int x = ws[t];
#pragma unroll
        for (int o = 1; o < 8; o <<= 1) {
            int y = __shfl_up_sync(0xffu, x, o, 8);
            if (t >= o) x += y;
        }
        ws[t] = x;
    }
    __syncthreads();
    int excl = incl - v + (w > 0 ? ws[w - 1] : 0);
    if (t < SCAN_BLOCKS) g_blocksum[t] = excl;
}
__global__ void scan_add() {
    int b = blockIdx.x, t = threadIdx.x;
    int i = b * 256 + t;
    if (i >= N_NODES) return;
    int off = g_offset[i] + g_blocksum[b];
    g_offset[i] = off;
    g_cursor[i] = off;
}
__global__ void scatter_kernel(const int* __restrict__ esrc, const int* __restrict__ edst,
                               const float* __restrict__ ew) {
    int i = blockIdx.x * blockDim.x + threadIdx.x;
    if (i >= N_EDGES) return;
    int d = edst[i];
    int pos = atomicAdd(&g_cursor[d], 1);
    g_sorted[pos] = make_int2(esrc[i], __float_as_int(ew[i]));
}

// ---------------- per-node max aggregation (fp16 table, 2-way ILP) ----------------
__global__ void agg_kernel(const float* __restrict__ Wm, const float* __restrict__ bm) {
    int gw = (blockIdx.x * blockDim.x + threadIdx.x) >> 5;
    int lane = threadIdx.x & 31;
    if (gw >= N_NODES) return;

    int start = g_offset[gw];
    int end = (gw + 1 < N_NODES ? g_offset[gw + 1] : N_EDGES);
    float4 outv = make_float4(0.f, 0.f, 0.f, 0.f);
    if (end > start) {
        float4 w4 = *(const float4*)(Wm + 256 * 128 + lane * 4);  // ww
        const float NI = -CUDART_INF_F;
        float4 m0 = make_float4(NI, NI, NI, NI);
        float4 m1 = make_float4(NI, NI, NI, NI);
        int e = start;
        for (; e + 2 <= end; e += 2) {
            int2 p0 = __ldg(&g_sorted[e]);
            int2 p1 = __ldg(&g_sorted[e + 1]);
            uint2 u0 = *(const uint2*)(g_Ps16 + (size_t)p0.x * HID + lane * 4);
            uint2 u1 = *(const uint2*)(g_Ps16 + (size_t)p1.x * HID + lane * 4);
            float w0 = __int_as_float(p0.y);
            float w1 = __int_as_float(p1.y);
            float2 a01 = __half22float2(*(__half2*)&u0.x);
            float2 a23 = __half22float2(*(__half2*)&u0.y);
            float2 b01 = __half22float2(*(__half2*)&u1.x);
            float2 b23 = __half22float2(*(__half2*)&u1.y);
            m0.x = fmaxf(m0.x, fmaf(w0, w4.x, a01.x));
            m0.y = fmaxf(m0.y, fmaf(w0, w4.y, a01.y));
            m0.z = fmaxf(m0.z, fmaf(w0, w4.z, a23.x));
            m0.w = fmaxf(m0.w, fmaf(w0, w4.w, a23.y));
            m1.x = fmaxf(m1.x, fmaf(w1, w4.x, b01.x));
            m1.y = fmaxf(m1.y, fmaf(w1, w4.y, b01.y));
            m1.z = fmaxf(m1.z, fmaf(w1, w4.z, b23.x));
            m1.w = fmaxf(m1.w, fmaf(w1, w4.w, b23.y));
        }
        if (e < end) {
            int2 p0 = __ldg(&g_sorted[e]);
            uint2 u0 = *(const uint2*)(g_Ps16 + (size_t)p0.x * HID + lane * 4);
            float w0 = __int_as_float(p0.y);
            float2 a01 = __half22float2(*(__half2*)&u0.x);
            float2 a23 = __half22float2(*(__half2*)&u0.y);
            m0.x = fmaxf(m0.x, fmaf(w0, w4.x, a01.x));
            m0.y = fmaxf(m0.y, fmaf(w0, w4.y, a01.y));
            m0.z = fmaxf(m0.z, fmaf(w0, w4.z, a23.x));
            m0.w = fmaxf(m0.w, fmaf(w0, w4.w, a23.y));
        }
        m0.x = fmaxf(m0.x, m1.x); m0.y = fmaxf(m0.y, m1.y);
        m0.z = fmaxf(m0.z, m1.z); m0.w = fmaxf(m0.w, m1.w);

        float4 q = *(const float4*)(g_P + (size_t)gw * PW + 128 + lane * 4);  // z@Wd
        float4 b = *(const float4*)(bm + lane * 4);
        outv.x = q.x + b.x + m0.x;
        outv.y = q.y + b.y + m0.y;
        outv.z = q.z + b.z + m0.z;
        outv.w = q.w + b.w + m0.w;
    }
    *(float4*)(g_agg + (size_t)gw * HID + lane * 4) = outv;
}

// ---------------- launch ----------------
extern "C" void kernel_launch(void* const* d_in, const int* in_sizes, int n_in,
                              void* d_out, int out_size) {
    const float* z    = (const float*)d_in[0];
    const float* ew   = (const float*)d_in[1];
    const int*   esrc = (const int*)d_in[2];
    const int*   edst = (const int*)d_in[3];
    const float* Wm   = (const float*)d_in[4];
    const float* bm   = (const float*)d_in[5];
    const float* W1   = (const float*)d_in[6];
    const float* b1   = (const float*)d_in[7];
    const float* W2   = (const float*)d_in[8];
    const float* b2   = (const float*)d_in[9];
    float* out = (float*)d_out;

    float *P, *AGG, *HIDN;
    cudaGetSymbolAddress((void**)&P, g_P);
    cudaGetSymbolAddress((void**)&AGG, g_agg);
    cudaGetSymbolAddress((void**)&HIDN, g_hidden);

    static cudaStream_t s2 = nullptr;
    static cudaEvent_t evFork = nullptr, evJoin = nullptr;
    static bool init_done = false;
    if (!init_done) {
        cudaFuncSetAttribute(mma_gemm, cudaFuncAttributeMaxDynamicSharedMemorySize, SM_TOTAL);
        cudaStreamCreateWithFlags(&s2, cudaStreamNonBlocking);
        cudaEventCreateWithFlags(&evFork, cudaEventDisableTiming);
        cudaEventCreateWithFlags(&evJoin, cudaEventDisableTiming);
        init_done = true;
    }

    const int NT = (N_NODES + 127) / 128;  // 391 row tiles

    // ---- fork: edge pipeline on s2, GEMM on main ----
    cudaEventRecord(evFork, 0);
    cudaStreamWaitEvent(s2, evFork, 0);

    zero_count_kernel<<<SCAN_BLOCKS, 256, 0, s2>>>();
    hist_kernel<<<N_EDGES / 256, 256, 0, s2>>>(edst);
    scan_local<<<SCAN_BLOCKS, 256, 0, s2>>>();
    scan_sums<<<1, 256, 0, s2>>>();
    scan_add<<<SCAN_BLOCKS, 256, 0, s2>>>();
    scatter_kernel<<<N_EDGES / 256, 256, 0, s2>>>(esrc, edst, ew);
    cudaEventRecord(evJoin, s2);

    // P[:,0:128)=z@Ws (+fp16 table), [128:256)=z@Wd, [256:384)=z@W1a
    mma_gemm<<<dim3(NT, 3), 256, SM_TOTAL>>>(
        z, Wm + 128 * 128, Wm, W1, nullptr, nullptr, 0, P, PW, N_NODES, 0, 1);

    // ---- join ----
    cudaStreamWaitEvent(0, evJoin, 0);

    agg_kernel<<<(N_NODES * 32 + 255) / 256, 256>>>(Wm, bm);

    // hidden = relu(agg @ W1b + b1 + P[:,256:384))
    mma_gemm<<<dim3(NT, 1), 256, SM_TOTAL>>>(
        AGG, W1 + 128 * 128, nullptr, nullptr, b1, P + 256, PW, HIDN, HID, N_NODES, 1, 0);

    // out = hidden @ W2 + b2
    mma_gemm<<<dim3(NT, 1), 256, SM_TOTAL>>>(
        HIDN, W2, nullptr, nullptr, b2, nullptr, 0, out, HID, N_NODES, 0, 0);
}

// round 9
// speedup vs baseline: 1.0286x; 1.0286x over previous
#include <cuda_runtime.h>
#include <cuda_bf16.h>
#include <cuda_fp16.h>
#include <cooperative_groups.h>
#include <math_constants.h>
#include <cstdint>

namespace cg = cooperative_groups;

#define N_NODES 50000
#define N_EDGES 800000
#define HID 128
#define PW 256   // [0:128)=z@Wd, [128:256)=z@W1a   (z@Ws lives only in g_Ps16)
#define SCAN_BLOCKS ((N_NODES + 255) / 256)   // 196

// ---------------- scratch ----------------
__device__ float  g_P[(size_t)N_NODES * PW];
__device__ __half g_Ps16[(size_t)N_NODES * HID];   // fp16 z@Ws for edge gather
__device__ float  g_agg[(size_t)N_NODES * HID];
__device__ int    g_count[N_NODES];
__device__ int    g_offset[N_NODES];
__device__ int    g_cursor[N_NODES];
__device__ int    g_blocksum[SCAN_BLOCKS];
__device__ int2   g_sorted[N_EDGES];               // (src, w bits)

// ---------------- mma.sync helpers (portable sm_80+ PTX) ----------------
__device__ __forceinline__ uint32_t smem_u32(const void* p) {
    uint32_t a;
    asm("{ .reg .u64 t; cvta.to.shared.u64 t, %1; cvt.u32.u64 %0, t; }" : "=r"(a) : "l"(p));
    return a;
}
__device__ __forceinline__ void ldsm_x4(uint32_t* r, uint32_t addr) {
    asm volatile("ldmatrix.sync.aligned.m8n8.x4.shared.b16 {%0,%1,%2,%3}, [%4];"
                 : "=r"(r[0]), "=r"(r[1]), "=r"(r[2]), "=r"(r[3]) : "r"(addr));
}
__device__ __forceinline__ void ldsm_x4_t(uint32_t* r, uint32_t addr) {
    asm volatile("ldmatrix.sync.aligned.m8n8.x4.trans.shared.b16 {%0,%1,%2,%3}, [%4];"
                 : "=r"(r[0]), "=r"(r[1]), "=r"(r[2]), "=r"(r[3]) : "r"(addr));
}
__device__ __forceinline__ void mma16816(float* c, const uint32_t* a, const uint32_t* b) {
    asm volatile(
        "mma.sync.aligned.m16n8k16.row.col.f32.bf16.bf16.f32 "
        "{%0,%1,%2,%3}, {%4,%5,%6,%7}, {%8,%9}, {%0,%1,%2,%3};"
        : "+f"(c[0]), "+f"(c[1]), "+f"(c[2]), "+f"(c[3])
        : "r"(a[0]), "r"(a[1]), "r"(a[2]), "r"(a[3]), "r"(b[0]), "r"(b[1]));
}
__device__ __forceinline__ uint32_t pack2(float x, float y) {
    __nv_bfloat162 h = __floats2bfloat162_rn(x, y);
    return *(uint32_t*)&h;
}
__device__ __forceinline__ float tobf(float x) {
    return __bfloat162float(__float2bfloat16(x));
}
// swizzled byte offset inside a [128][128] bf16 tile (256B rows)
__device__ __forceinline__ uint32_t swz(int row, int col) {
    return (uint32_t)(row * 256 + ((((col >> 3) ^ (row & 7))) << 4) + (col & 7) * 2);
}

// smem plan
#define SM_AHI 0
#define SM_ALO 32768
#define SM_BHI 65536
#define SM_BLO 98304
#define SM_TOTAL 131072
#define SM_B2H 131072
#define SM_B2L 163840
#define SM_T_TOTAL 196608

// ---- shared building blocks ----
__device__ __forceinline__ void conv_A(const float* __restrict__ A, int bm0, int M,
                                       char* smem, int tid) {
#pragma unroll
    for (int i = 0; i < 32; i++) {
        int p = tid + i * 256;
        int row = p >> 6, col = (p & 63) * 2;
        float2 v = make_float2(0.f, 0.f);
        int gr = bm0 + row;
        if (gr < M) v = *(const float2*)(A + (size_t)gr * 128 + col);
        float hx = tobf(v.x), hy = tobf(v.y);
        uint32_t off = swz(row, col);
        *(uint32_t*)(smem + SM_AHI + off) = pack2(hx, hy);
        *(uint32_t*)(smem + SM_ALO + off) = pack2(v.x - hx, v.y - hy);
    }
}
__device__ __forceinline__ void conv_B(const float* __restrict__ B,
                                       char* smem, int offH, int offL, int tid) {
#pragma unroll
    for (int i = 0; i < 32; i++) {
        int p = tid + i * 256;
        int row = p >> 6, col = (p & 63) * 2;
        float2 v = *(const float2*)(B + (size_t)row * 128 + col);
        float hx = tobf(v.x), hy = tobf(v.y);
        uint32_t off = swz(row, col);
        *(uint32_t*)(smem + offH + off) = pack2(hx, hy);
        *(uint32_t*)(smem + offL + off) = pack2(v.x - hx, v.y - hy);
    }
}
__device__ __forceinline__ void mma_stage(uint32_t sb, int bHo, int bLo,
                                          int wm, int wn, int lane, float (&acc)[4][4][4]) {
    const int sub = lane >> 3;
    const int l7 = lane & 7;
    const int radd = (sub & 1) * 8;
    const int cadd = (sub >> 1) * 8;
#pragma unroll
    for (int ks = 0; ks < 8; ks++) {
        const int k0 = ks * 16;
        uint32_t aH[4][4], aL[4][4], bH[2][4], bL[2][4];
#pragma unroll
        for (int mt = 0; mt < 4; mt++) {
            uint32_t o = swz(wm * 64 + mt * 16 + l7 + radd, k0 + cadd);
            ldsm_x4(aH[mt], sb + SM_AHI + o);
            ldsm_x4(aL[mt], sb + SM_ALO + o);
        }
#pragma unroll
        for (int pr = 0; pr < 2; pr++) {
            uint32_t o = swz(k0 + l7 + radd, wn * 32 + pr * 16 + cadd);
            ldsm_x4_t(bH[pr], sb + bHo + o);
            ldsm_x4_t(bL[pr], sb + bLo + o);
        }
#pragma unroll
        for (int mt = 0; mt < 4; mt++)
#pragma unroll
            for (int nt = 0; nt < 4; nt++) {
                const uint32_t* bh = &bH[nt >> 1][(nt & 1) * 2];
                const uint32_t* bl = &bL[nt >> 1][(nt & 1) * 2];
                mma16816(acc[mt][nt], aH[mt], bh);
                mma16816(acc[mt][nt], aH[mt], bl);
                mma16816(acc[mt][nt], aL[mt], bh);
            }
    }
}

// ---------------- GEMM over z: by=0 -> z@Ws (fp16 table only); by=1 -> z@Wd; by=2 -> z@W1a
__global__ __launch_bounds__(256)
void gemm_z(const float* __restrict__ z, const float* __restrict__ Wm,
            const float* __restrict__ W1, int M)
{
    extern __shared__ char smem[];
    const uint32_t sb = smem_u32(smem);
    const int tid = threadIdx.x;
    const int wid = tid >> 5;
    const int lane = tid & 31;
    const int bm0 = blockIdx.x * 128;
    const int by = blockIdx.y;
    const float* B = (by == 0) ? (Wm + 128 * 128) : ((by == 1) ? Wm : W1);

    conv_A(z, bm0, M, smem, tid);
    conv_B(B, smem, SM_BHI, SM_BLO, tid);
    __syncthreads();

    const int wm = wid & 1, wn = wid >> 1;
    float acc[4][4][4];
#pragma unroll
    for (int mt = 0; mt < 4; mt++)
#pragma unroll
        for (int nt = 0; nt < 4; nt++)
#pragma unroll
            for (int j = 0; j < 4; j++) acc[mt][nt][j] = 0.f;

    mma_stage(sb, SM_BHI, SM_BLO, wm, wn, lane, acc);

    const int g = lane >> 2, tg = lane & 3;
#pragma unroll
    for (int mt = 0; mt < 4; mt++)
#pragma unroll
        for (int half = 0; half < 2; half++) {
            int r = bm0 + wm * 64 + mt * 16 + g + half * 8;
            if (r >= M) continue;
#pragma unroll
            for (int nt = 0; nt < 4; nt++) {
                int lc = wn * 32 + nt * 8 + 2 * tg;
                float vx = acc[mt][nt][half * 2 + 0];
                float vy = acc[mt][nt][half * 2 + 1];
                if (by == 0) {
                    *(__half2*)(g_Ps16 + (size_t)r * HID + lc) = __floats2half2_rn(vx, vy);
                } else {
                    float* orow = g_P + (size_t)r * PW + (by - 1) * 128;
                    *(float2*)(orow + lc) = make_float2(vx, vy);
                }
            }
        }
}

// ---------------- fused tail: out = relu(agg@W1b + P[:,128:256) + b1) @ W2 + b2 ----------------
__global__ __launch_bounds__(256)
void gemm_tail(const float* __restrict__ W1b, const float* __restrict__ b1,
               const float* __restrict__ W2, const float* __restrict__ b2,
               float* __restrict__ out, int M)
{
    extern __shared__ char smem[];
    const uint32_t sb = smem_u32(smem);
    const int tid = threadIdx.x;
    const int wid = tid >> 5;
    const int lane = tid & 31;
    const int bm0 = blockIdx.x * 128;
    const int wm = wid & 1, wn = wid >> 1;
    const int g = lane >> 2, tg = lane & 3;

    conv_A(g_agg, bm0, M, smem, tid);
    conv_B(W1b, smem, SM_BHI, SM_BLO, tid);
    conv_B(W2,  smem, SM_B2H, SM_B2L, tid);
    __syncthreads();

    float acc[4][4][4];
#pragma unroll
    for (int mt = 0; mt < 4; mt++)
#pragma unroll
        for (int nt = 0; nt < 4; nt++)
#pragma unroll
            for (int j = 0; j < 4; j++) acc[mt][nt][j] = 0.f;

    mma_stage(sb, SM_BHI, SM_BLO, wm, wn, lane, acc);
    __syncthreads();   // everyone done reading A smem before overwrite

    // hidden = relu(acc + b1 + P[:,128:256)) -> split bf16 back into A smem
#pragma unroll
    for (int mt = 0; mt < 4; mt++)
#pragma unroll
        for (int half = 0; half < 2; half++) {
            int lr = wm * 64 + mt * 16 + g + half * 8;
            int r = bm0 + lr;
            const float* crow = (r < M) ? (g_P + (size_t)r * PW + 128) : nullptr;
#pragma unroll
            for (int nt = 0; nt < 4; nt++) {
                int lc = wn * 32 + nt * 8 + 2 * tg;
                float vx = acc[mt][nt][half * 2 + 0] + b1[lc];
                float vy = acc[mt][nt][half * 2 + 1] + b1[lc + 1];
                if (crow) { vx += crow[lc]; vy += crow[lc + 1]; }
                vx = fmaxf(vx, 0.f); vy = fmaxf(vy, 0.f);
                float hx = tobf(vx), hy = tobf(vy);
                uint32_t off = swz(lr, lc);
                *(uint32_t*)(smem + SM_AHI + off) = pack2(hx, hy);
                *(uint32_t*)(smem + SM_ALO + off) = pack2(vx - hx, vy - hy);
            }
        }
    __syncthreads();

#pragma unroll
    for (int mt = 0; mt < 4; mt++)
#pragma unroll
        for (int nt = 0; nt < 4; nt++)
#pragma unroll
            for (int j = 0; j < 4; j++) acc[mt][nt][j] = 0.f;

    mma_stage(sb, SM_B2H, SM_B2L, wm, wn, lane, acc);

#pragma unroll
    for (int mt = 0; mt < 4; mt++)
#pragma unroll
        for (int half = 0; half < 2; half++) {
            int r = bm0 + wm * 64 + mt * 16 + g + half * 8;
            if (r >= M) continue;
            float* orow = out + (size_t)r * HID;
#pragma unroll
            for (int nt = 0; nt < 4; nt++) {
                int lc = wn * 32 + nt * 8 + 2 * tg;
                float2 v;
                v.x = acc[mt][nt][half * 2 + 0] + b2[lc];
                v.y = acc[mt][nt][half * 2 + 1] + b2[lc + 1];
                *(float2*)(orow + lc) = v;
            }
        }
}

// ---------------- fused edge pipeline (cooperative): zero+hist+scan+scatter ----------------
__global__ void prep_kernel(const int* __restrict__ esrc, const int* __restrict__ edst,
                            const float* __restrict__ ew)
{
    cg::grid_group grid = cg::this_grid();
    const int bid = blockIdx.x, t = threadIdx.x;
    const int gt = bid * 256 + t;
    const int gsz = gridDim.x * 256;

    // phase 0: zero counts
    for (int i = gt; i < N_NODES; i += gsz) g_count[i] = 0;
    grid.sync();

    // phase 1: histogram
    for (int i = gt; i < N_EDGES; i += gsz) atomicAdd(&g_count[edst[i]], 1);
    grid.sync();

    // phase 2: block-local scan (blocks 0..SCAN_BLOCKS-1)
    __shared__ int ws[8];
    if (bid < SCAN_BLOCKS) {
        int i = bid * 256 + t;
        int v = (i < N_NODES) ? g_count[i] : 0;
        int lane = t & 31, w = t >> 5;
        int incl = v;
#pragma unroll
        for (int o = 1; o < 32; o <<= 1) {
            int y = __shfl_up_sync(0xffffffffu, incl, o);
            if (lane >= o) incl += y;
        }
        if (lane == 31) ws[w] = incl;
        __syncthreads();
        if (t < 8) {
            int x = ws[t];
#pragma unroll
            for (int o = 1; o < 8; o <<= 1) {
                int y = __shfl_up_sync(0xffu, x, o, 8);
                if (t >= o) x += y;
            }
            ws[t] = x;
        }
        __syncthreads();
        int excl = incl - v + (w > 0 ? ws[w - 1] : 0);
        if (i < N_NODES) g_offset[i] = excl;
        if (t == 255) g_blocksum[bid] = ws[7];
    }
    grid.sync();

    // phase 3: scan block sums (block 0)
    if (bid == 0) {
        int v = (t < SCAN_BLOCKS) ? g_blocksum[t] : 0;
        int lane = t & 31, w = t >> 5;
        int incl = v;
#pragma unroll
        for (int o = 1; o < 32; o <<= 1) {
            int y = __shfl_up_sync(0xffffffffu, incl, o);
            if (lane >= o) incl += y;
        }
        if (lane == 31) ws[w] = incl;
        __syncthreads();
        if (t < 8) {
            int x = ws[t];
#pragma unroll
            for (int o = 1; o < 8; o <<= 1) {
                int y = __shfl_up_sync(0xffu, x, o, 8);
                if (t >= o) x += y;
            }
            ws[t] = x;
        }
        __syncthreads();
        int excl = incl - v + (w > 0 ? ws[w - 1] : 0);
        if (t < SCAN_BLOCKS) g_blocksum[t] = excl;
    }
    grid.sync();

    // phase 4: add block offsets, init cursor
    if (bid < SCAN_BLOCKS) {
        int i = bid * 256 + t;
        if (i < N_NODES) {
            int off = g_offset[i] + g_blocksum[bid];
            g_offset[i] = off;
            g_cursor[i] = off;
        }
    }
    grid.sync();

    // phase 5: scatter
    for (int i = gt; i < N_EDGES; i += gsz) {
        int d = edst[i];
        int pos = atomicAdd(&g_cursor[d], 1);
        g_sorted[pos] = make_int2(esrc[i], __float_as_int(ew[i]));
    }
}

// ---------------- per-node max aggregation (fp16 table, 2-way ILP) ----------------
__global__ void agg_kernel(const float* __restrict__ Wm, const float* __restrict__ bm) {
    int gw = (blockIdx.x * blockDim.x + threadIdx.x) >> 5;
    int lane = threadIdx.x & 31;
    if (gw >= N_NODES) return;

    int start = g_offset[gw];
    int end = (gw + 1 < N_NODES ? g_offset[gw + 1] : N_EDGES);
    float4 outv = make_float4(0.f, 0.f, 0.f, 0.f);
    if (end > start) {
        float4 w4 = *(const float4*)(Wm + 256 * 128 + lane * 4);  // ww
        const float NI = -CUDART_INF_F;
        float4 m0 = make_float4(NI, NI, NI, NI);
        float4 m1 = make_float4(NI, NI, NI, NI);
        int e = start;
        for (; e + 2 <= end; e += 2) {
            int2 p0 = __ldg(&g_sorted[e]);
            int2 p1 = __ldg(&g_sorted[e + 1]);
            uint2 u0 = *(const uint2*)(g_Ps16 + (size_t)p0.x * HID + lane * 4);
            uint2 u1 = *(const uint2*)(g_Ps16 + (size_t)p1.x * HID + lane * 4);
            float w0 = __int_as_float(p0.y);
            float w1 = __int_as_float(p1.y);
            float2 a01 = __half22float2(*(__half2*)&u0.x);
            float2 a23 = __half22float2(*(__half2*)&u0.y);
            float2 b01 = __half22float2(*(__half2*)&u1.x);
            float2 b23 = __half22float2(*(__half2*)&u1.y);
            m0.x = fmaxf(m0.x, fmaf(w0, w4.x, a01.x));
            m0.y = fmaxf(m0.y, fmaf(w0, w4.y, a01.y));
            m0.z = fmaxf(m0.z, fmaf(w0, w4.z, a23.x));
            m0.w = fmaxf(m0.w, fmaf(w0, w4.w, a23.y));
            m1.x = fmaxf(m1.x, fmaf(w1, w4.x, b01.x));
            m1.y = fmaxf(m1.y, fmaf(w1, w4.y, b01.y));
            m1.z = fmaxf(m1.z, fmaf(w1, w4.z, b23.x));
            m1.w = fmaxf(m1.w, fmaf(w1, w4.w, b23.y));
        }
        if (e < end) {
            int2 p0 = __ldg(&g_sorted[e]);
            uint2 u0 = *(const uint2*)(g_Ps16 + (size_t)p0.x * HID + lane * 4);
            float w0 = __int_as_float(p0.y);
            float2 a01 = __half22float2(*(__half2*)&u0.x);
            float2 a23 = __half22float2(*(__half2*)&u0.y);
            m0.x = fmaxf(m0.x, fmaf(w0, w4.x, a01.x));
            m0.y = fmaxf(m0.y, fmaf(w0, w4.y, a01.y));
            m0.z = fmaxf(m0.z, fmaf(w0, w4.z, a23.x));
            m0.w = fmaxf(m0.w, fmaf(w0, w4.w, a23.y));
        }
        m0.x = fmaxf(m0.x, m1.x); m0.y = fmaxf(m0.y, m1.y);
        m0.z = fmaxf(m0.z, m1.z); m0.w = fmaxf(m0.w, m1.w);

        float4 q = *(const float4*)(g_P + (size_t)gw * PW + lane * 4);  // z@Wd
        float4 b = *(const float4*)(bm + lane * 4);
        outv.x = q.x + b.x + m0.x;
        outv.y = q.y + b.y + m0.y;
        outv.z = q.z + b.z + m0.z;
        outv.w = q.w + b.w + m0.w;
    }
    *(float4*)(g_agg + (size_t)gw * HID + lane * 4) = outv;
}

// ---------------- launch ----------------
extern "C" void kernel_launch(void* const* d_in, const int* in_sizes, int n_in,
                              void* d_out, int out_size) {
    const float* z    = (const float*)d_in[0];
    const float* ew   = (const float*)d_in[1];
    const int*   esrc = (const int*)d_in[2];
    const int*   edst = (const int*)d_in[3];
    const float* Wm   = (const float*)d_in[4];
    const float* bm   = (const float*)d_in[5];
    const float* W1   = (const float*)d_in[6];
    const float* b1   = (const float*)d_in[7];
    const float* W2   = (const float*)d_in[8];
    const float* b2   = (const float*)d_in[9];
    float* out = (float*)d_out;

    static int prep_blocks = 0;
    static bool init_done = false;
    if (!init_done) {
        cudaFuncSetAttribute(gemm_z,    cudaFuncAttributeMaxDynamicSharedMemorySize, SM_TOTAL);
        cudaFuncSetAttribute(gemm_tail, cudaFuncAttributeMaxDynamicSharedMemorySize, SM_T_TOTAL);
        int nb = 0, nsm = 0;
        cudaOccupancyMaxActiveBlocksPerMultiprocessor(&nb, prep_kernel, 256, 0);
        cudaDeviceGetAttribute(&nsm, cudaDevAttrMultiProcessorCount, 0);
        prep_blocks = nb * nsm;
        if (prep_blocks < SCAN_BLOCKS) prep_blocks = SCAN_BLOCKS;  // scan needs 196 blocks
        init_done = true;
    }

    const int NT = (N_NODES + 127) / 128;  // 391 row tiles

    // 1. fused edge counting sort (cooperative)
    {
        void* args[3] = { (void*)&esrc, (void*)&edst, (void*)&ew };
        cudaLaunchCooperativeKernel((void*)prep_kernel, dim3(prep_blocks), dim3(256), args, 0, 0);
    }

    // 2. z GEMMs: by0 -> fp16 z@Ws table; by1 -> z@Wd; by2 -> z@W1a
    gemm_z<<<dim3(NT, 3), 256, SM_TOTAL>>>(z, Wm, W1, N_NODES);

    // 3. aggregation
    agg_kernel<<<(N_NODES * 32 + 255) / 256, 256>>>(Wm, bm);

    // 4. fused tail: out = relu(agg@W1b + P3 + b1) @ W2 + b2
    gemm_tail<<<NT, 256, SM_T_TOTAL>>>(W1 + 128 * 128, b1, W2, b2, out, N_NODES);
}

// round 12
// speedup vs baseline: 1.0551x; 1.0258x over previous
#include <cuda_runtime.h>
#include <cuda_bf16.h>
#include <cuda_fp16.h>
#include <cooperative_groups.h>
#include <math_constants.h>
#include <cstdint>

namespace cg = cooperative_groups;

#define N_NODES 50000
#define N_EDGES 800000
#define HID 128
#define PW 256   // [0:128)=z@Wd, [128:256)=z@W1a
#define SCAN_BLOCKS ((N_NODES + 255) / 256)   // 196

// ---------------- scratch ----------------
__device__ float  g_P[(size_t)N_NODES * PW];
__device__ __half g_Ps16[(size_t)N_NODES * HID];   // fp16 z@Ws for edge gather
__device__ float  g_agg[(size_t)N_NODES * HID];
__device__ int    g_count[N_NODES];
__device__ int    g_offset[N_NODES];
__device__ int    g_cursor[N_NODES];
__device__ int    g_blocksum[SCAN_BLOCKS];
__device__ int2   g_sorted[N_EDGES];               // (src, w bits)
// pre-split, pre-swizzled weights: 0=Ws 1=Wd 2=W1a 3=W1b 4=W2
__device__ __nv_bfloat16 g_WH[5][16384];
__device__ __nv_bfloat16 g_WL[5][16384];

// ---------------- mma.sync helpers (portable sm_80+ PTX) ----------------
__device__ __forceinline__ uint32_t smem_u32(const void* p) {
    uint32_t a;
    asm("{ .reg .u64 t; cvta.to.shared.u64 t, %1; cvt.u32.u64 %0, t; }" : "=r"(a) : "l"(p));
    return a;
}
__device__ __forceinline__ void ldsm_x4(uint32_t* r, uint32_t addr) {
    asm volatile("ldmatrix.sync.aligned.m8n8.x4.shared.b16 {%0,%1,%2,%3}, [%4];"
                 : "=r"(r[0]), "=r"(r[1]), "=r"(r[2]), "=r"(r[3]) : "r"(addr));
}
__device__ __forceinline__ void ldsm_x4_t(uint32_t* r, uint32_t addr) {
    asm volatile("ldmatrix.sync.aligned.m8n8.x4.trans.shared.b16 {%0,%1,%2,%3}, [%4];"
                 : "=r"(r[0]), "=r"(r[1]), "=r"(r[2]), "=r"(r[3]) : "r"(addr));
}
__device__ __forceinline__ void mma16816(float* c, const uint32_t* a, const uint32_t* b) {
    asm volatile(
        "mma.sync.aligned.m16n8k16.row.col.f32.bf16.bf16.f32 "
        "{%0,%1,%2,%3}, {%4,%5,%6,%7}, {%8,%9}, {%0,%1,%2,%3};"
        : "+f"(c[0]), "+f"(c[1]), "+f"(c[2]), "+f"(c[3])
        : "r"(a[0]), "r"(a[1]), "r"(a[2]), "r"(a[3]), "r"(b[0]), "r"(b[1]));
}
__device__ __forceinline__ uint32_t pack2(float x, float y) {
    __nv_bfloat162 h = __floats2bfloat162_rn(x, y);
    return *(uint32_t*)&h;
}
__device__ __forceinline__ float tobf(float x) {
    return __bfloat162float(__float2bfloat16(x));
}
// swizzled byte offset inside a [128][128] bf16 tile (256B rows)
__device__ __forceinline__ uint32_t swz(int row, int col) {
    return (uint32_t)(row * 256 + ((((col >> 3) ^ (row & 7))) << 4) + (col & 7) * 2);
}

// smem plan
#define SM_AHI 0
#define SM_ALO 32768
#define SM_BHI 65536
#define SM_BLO 98304
#define SM_TOTAL 131072
#define SM_B2H 131072
#define SM_B2L 163840
#define SM_T_TOTAL 196608

// ---- building blocks ----
__device__ __forceinline__ void conv_A(const float* __restrict__ A, int bm0, int M,
                                       char* smem, int tid) {
#pragma unroll
    for (int i = 0; i < 32; i++) {
        int p = tid + i * 256;
        int row = p >> 6, col = (p & 63) * 2;
        float2 v = make_float2(0.f, 0.f);
        int gr = bm0 + row;
        if (gr < M) v = *(const float2*)(A + (size_t)gr * 128 + col);
        float hx = tobf(v.x), hy = tobf(v.y);
        uint32_t off = swz(row, col);
        *(uint32_t*)(smem + SM_AHI + off) = pack2(hx, hy);
        *(uint32_t*)(smem + SM_ALO + off) = pack2(v.x - hx, v.y - hy);
    }
}
// copy pre-split pre-swizzled weight blob into smem (32 KB each for hi and lo)
__device__ __forceinline__ void copy_B(int m, char* smem, int offH, int offL, int tid) {
    const uint4* __restrict__ sh = (const uint4*)g_WH[m];
    const uint4* __restrict__ sl = (const uint4*)g_WL[m];
    uint4* dh = (uint4*)(smem + offH);
    uint4* dl = (uint4*)(smem + offL);
#pragma unroll
    for (int i = 0; i < 8; i++) {
        dh[tid + i * 256] = sh[tid + i * 256];
        dl[tid + i * 256] = sl[tid + i * 256];
    }
}
__device__ __forceinline__ void mma_stage(uint32_t sb, int bHo, int bLo,
                                          int wm, int wn, int lane, float (&acc)[4][4][4]) {
    const int sub = lane >> 3;
    const int l7 = lane & 7;
    const int radd = (sub & 1) * 8;
    const int cadd = (sub >> 1) * 8;
#pragma unroll
    for (int ks = 0; ks < 8; ks++) {
        const int k0 = ks * 16;
        uint32_t aH[4][4], aL[4][4], bH[2][4], bL[2][4];
#pragma unroll
        for (int mt = 0; mt < 4; mt++) {
            uint32_t o = swz(wm * 64 + mt * 16 + l7 + radd, k0 + cadd);
            ldsm_x4(aH[mt], sb + SM_AHI + o);
            ldsm_x4(aL[mt], sb + SM_ALO + o);
        }
#pragma unroll
        for (int pr = 0; pr < 2; pr++) {
            uint32_t o = swz(k0 + l7 + radd, wn * 32 + pr * 16 + cadd);
            ldsm_x4_t(bH[pr], sb + bHo + o);
            ldsm_x4_t(bL[pr], sb + bLo + o);
        }
#pragma unroll
        for (int mt = 0; mt < 4; mt++)
#pragma unroll
            for (int nt = 0; nt < 4; nt++) {
                const uint32_t* bh = &bH[nt >> 1][(nt & 1) * 2];
                const uint32_t* bl = &bL[nt >> 1][(nt & 1) * 2];
                mma16816(acc[mt][nt], aH[mt], bh);
                mma16816(acc[mt][nt], aH[mt], bl);
                mma16816(acc[mt][nt], aL[mt], bh);
            }
    }
}

// ---------------- GEMM over z: by=0 -> z@Ws (fp16 table); by=1 -> z@Wd; by=2 -> z@W1a
__global__ __launch_bounds__(256)
void gemm_z(const float* __restrict__ z, int M)
{
    extern __shared__ char smem[];
    const uint32_t sb = smem_u32(smem);
    const int tid = threadIdx.x;
    const int wid = tid >> 5;
    const int lane = tid & 31;
    const int bm0 = blockIdx.x * 128;
    const int by = blockIdx.y;

    conv_A(z, bm0, M, smem, tid);
    copy_B(by, smem, SM_BHI, SM_BLO, tid);
    __syncthreads();

    const int wm = wid & 1, wn = wid >> 1;
    float acc[4][4][4];
#pragma unroll
    for (int mt = 0; mt < 4; mt++)
#pragma unroll
        for (int nt = 0; nt < 4; nt++)
#pragma unroll
            for (int j = 0; j < 4; j++) acc[mt][nt][j] = 0.f;

    mma_stage(sb, SM_BHI, SM_BLO, wm, wn, lane, acc);

    const int g = lane >> 2, tg = lane & 3;
#pragma unroll
    for (int mt = 0; mt < 4; mt++)
#pragma unroll
        for (int half = 0; half < 2; half++) {
            int r = bm0 + wm * 64 + mt * 16 + g + half * 8;
            if (r >= M) continue;
#pragma unroll
            for (int nt = 0; nt < 4; nt++) {
                int lc = wn * 32 + nt * 8 + 2 * tg;
                float vx = acc[mt][nt][half * 2 + 0];
                float vy = acc[mt][nt][half * 2 + 1];
                if (by == 0) {
                    *(__half2*)(g_Ps16 + (size_t)r * HID + lc) = __floats2half2_rn(vx, vy);
                } else {
                    float* orow = g_P + (size_t)r * PW + (by - 1) * 128;
                    *(float2*)(orow + lc) = make_float2(vx, vy);
                }
            }
        }
}

// ---------------- fused tail: out = relu(agg@W1b + P[:,128:256) + b1) @ W2 + b2 ----------------
__global__ __launch_bounds__(256)
void gemm_tail(const float* __restrict__ b1, const float* __restrict__ b2,
               float* __restrict__ out, int M)
{
    extern __shared__ char smem[];
    const uint32_t sb = smem_u32(smem);
    const int tid = threadIdx.x;
    const int wid = tid >> 5;
    const int lane = tid & 31;
    const int bm0 = blockIdx.x * 128;
    const int wm = wid & 1, wn = wid >> 1;
    const int g = lane >> 2, tg = lane & 3;

    conv_A(g_agg, bm0, M, smem, tid);
    copy_B(3, smem, SM_BHI, SM_BLO, tid);   // W1b
    copy_B(4, smem, SM_B2H, SM_B2L, tid);   // W2
    __syncthreads();

    float acc[4][4][4];
#pragma unroll
    for (int mt = 0; mt < 4; mt++)
#pragma unroll
        for (int nt = 0; nt < 4; nt++)
#pragma unroll
            for (int j = 0; j < 4; j++) acc[mt][nt][j] = 0.f;

    mma_stage(sb, SM_BHI, SM_BLO, wm, wn, lane, acc);
    __syncthreads();   // all reads of A smem done before overwrite

    // hidden = relu(acc + b1 + P[:,128:256)) -> split bf16 back into A smem
#pragma unroll
    for (int mt = 0; mt < 4; mt++)
#pragma unroll
        for (int half = 0; half < 2; half++) {
            int lr = wm * 64 + mt * 16 + g + half * 8;
            int r = bm0 + lr;
            const float* crow = (r < M) ? (g_P + (size_t)r * PW + 128) : nullptr;
#pragma unroll
            for (int nt = 0; nt < 4; nt++) {
                int lc = wn * 32 + nt * 8 + 2 * tg;
                float vx = acc[mt][nt][half * 2 + 0] + b1[lc];
                float vy = acc[mt][nt][half * 2 + 1] + b1[lc + 1];
                if (crow) { vx += crow[lc]; vy += crow[lc + 1]; }
                vx = fmaxf(vx, 0.f); vy = fmaxf(vy, 0.f);
                float hx = tobf(vx), hy = tobf(vy);
                uint32_t off = swz(lr, lc);
                *(uint32_t*)(smem + SM_AHI + off) = pack2(hx, hy);
                *(uint32_t*)(smem + SM_ALO + off) = pack2(vx - hx, vy - hy);
            }
        }
    __syncthreads();

#pragma unroll
    for (int mt = 0; mt < 4; mt++)
#pragma unroll
        for (int nt = 0; nt < 4; nt++)
#pragma unroll
            for (int j = 0; j < 4; j++) acc[mt][nt][j] = 0.f;

    mma_stage(sb, SM_B2H, SM_B2L, wm, wn, lane, acc);

#pragma unroll
    for (int mt = 0; mt < 4; mt++)
#pragma unroll
        for (int half = 0; half < 2; half++) {
            int r = bm0 + wm * 64 + mt * 16 + g + half * 8;
            if (r >= M) continue;
            float* orow = out + (size_t)r * HID;
#pragma unroll
            for (int nt = 0; nt < 4; nt++) {
                int lc = wn * 32 + nt * 8 + 2 * tg;
                float2 v;
                v.x = acc[mt][nt][half * 2 + 0] + b2[lc];
                v.y = acc[mt][nt][half * 2 + 1] + b2[lc + 1];
                *(float2*)(orow + lc) = v;
            }
        }
}

// ---------------- fused prep (cooperative): W-split + zero+hist+scan+scatter ----------------
__global__ void prep_kernel(const int* __restrict__ esrc, const int* __restrict__ edst,
                            const float* __restrict__ ew,
                            const float* __restrict__ Wm, const float* __restrict__ W1,
                            const float* __restrict__ W2)
{
    cg::grid_group grid = cg::this_grid();
    const int bid = blockIdx.x, t = threadIdx.x;
    const int gt = bid * 256 + t;
    const int gsz = gridDim.x * 256;

    // phase -1: split+swizzle the 5 weight matrices (no sync needed w.r.t. phase 0/1)
    for (int idx = gt; idx < 5 * 16384; idx += gsz) {
        int m = idx >> 14;
        int p = idx & 16383;
        int row = p >> 7, col = p & 127;
        const float* src = (m == 0) ? (Wm + 128 * 128)
                         : (m == 1) ? Wm
                         : (m == 2) ? W1
                         : (m == 3) ? (W1 + 128 * 128) : W2;
        float v = src[row * 128 + col];
        float h = tobf(v);
        uint32_t off = swz(row, col);   // byte offset
        *(__nv_bfloat16*)((char*)g_WH[m] + off) = __float2bfloat16(h);
        *(__nv_bfloat16*)((char*)g_WL[m] + off) = __float2bfloat16(v - h);
    }

    // phase 0: zero counts
    for (int i = gt; i < N_NODES; i += gsz) g_count[i] = 0;
    grid.sync();

    // phase 1: histogram
    for (int i = gt; i < N_EDGES; i += gsz) atomicAdd(&g_count[edst[i]], 1);
    grid.sync();

    // phase 2: block-local scan
    __shared__ int ws[8];
    if (bid < SCAN_BLOCKS) {
        int i = bid * 256 + t;
        int v = (i < N_NODES) ? g_count[i] : 0;
        int lane = t & 31, w = t >> 5;
        int incl = v;
#pragma unroll
        for (int o = 1; o < 32; o <<= 1) {
            int y = __shfl_up_sync(0xffffffffu, incl, o);
            if (lane >= o) incl += y;
        }
        if (lane == 31) ws[w] = incl;
        __syncthreads();
        if (t < 8) {
            int x = ws[t];
#pragma unroll
            for (int o = 1; o < 8; o <<= 1) {
                int y = __shfl_up_sync(0xffu, x, o, 8);
                if (t >= o) x += y;
            }
            ws[t] = x;
        }
        __syncthreads();
        int excl = incl - v + (w > 0 ? ws[w - 1] : 0);
        if (i < N_NODES) g_offset[i] = excl;
        if (t == 255) g_blocksum[bid] = ws[7];
    }
    grid.sync();

    // phase 3: scan block sums
    if (bid == 0) {
        int v = (t < SCAN_BLOCKS) ? g_blocksum[t] : 0;
        int lane = t & 31, w = t >> 5;
        int incl = v;
#pragma unroll
        for (int o = 1; o < 32; o <<= 1) {
            int y = __shfl_up_sync(0xffffffffu, incl, o);
            if (lane >= o) incl += y;
        }
        if (lane == 31) ws[w] = incl;
        __syncthreads();
        if (t < 8) {
            int x = ws[t];
#pragma unroll
            for (int o = 1; o < 8; o <<= 1) {
                int y = __shfl_up_sync(0xffu, x, o, 8);
                if (t >= o) x += y;
            }
            ws[t] = x;
        }
        __syncthreads();
        int excl = incl - v + (w > 0 ? ws[w - 1] : 0);
        if (t < SCAN_BLOCKS) g_blocksum[t] = excl;
    }
    grid.sync();

    // phase 4: add block offsets, init cursor
    if (bid < SCAN_BLOCKS) {
        int i = bid * 256 + t;
        if (i < N_NODES) {
            int off = g_offset[i] + g_blocksum[bid];
            g_offset[i] = off;
            g_cursor[i] = off;
        }
    }
    grid.sync();

    // phase 5: scatter
    for (int i = gt; i < N_EDGES; i += gsz) {
        int d = edst[i];
        int pos = atomicAdd(&g_cursor[d], 1);
        g_sorted[pos] = make_int2(esrc[i], __float_as_int(ew[i]));
    }
}

// ---------------- per-node max aggregation (fp16 table, 2-way ILP) ----------------
__global__ void agg_kernel(const float* __restrict__ Wm, const float* __restrict__ bm) {
    int gw = (blockIdx.x * blockDim.x + threadIdx.x) >> 5;
    int lane = threadIdx.x & 31;
    if (gw >= N_NODES) return;

    int start = g_offset[gw];
    int end = (gw + 1 < N_NODES ? g_offset[gw + 1] : N_EDGES);
    float4 outv = make_float4(0.f, 0.f, 0.f, 0.f);
    if (end > start) {
        float4 w4 = *(const float4*)(Wm + 256 * 128 + lane * 4);  // ww
        const float NI = -CUDART_INF_F;
        float4 m0 = make_float4(NI, NI, NI, NI);
        float4 m1 = make_float4(NI, NI, NI, NI);
        int e = start;
        for (; e + 2 <= end; e += 2) {
            int2 p0 = __ldg(&g_sorted[e]);
            int2 p1 = __ldg(&g_sorted[e + 1]);
            uint2 u0 = *(const uint2*)(g_Ps16 + (size_t)p0.x * HID + lane * 4);
            uint2 u1 = *(const uint2*)(g_Ps16 + (size_t)p1.x * HID + lane * 4);
            float w0 = __int_as_float(p0.y);
            float w1 = __int_as_float(p1.y);
            float2 a01 = __half22float2(*(__half2*)&u0.x);
            float2 a23 = __half22float2(*(__half2*)&u0.y);
            float2 b01 = __half22float2(*(__half2*)&u1.x);
            float2 b23 = __half22float2(*(__half2*)&u1.y);
            m0.x = fmaxf(m0.x, fmaf(w0, w4.x, a01.x));
            m0.y = fmaxf(m0.y, fmaf(w0, w4.y, a01.y));
            m0.z = fmaxf(m0.z, fmaf(w0, w4.z, a23.x));
            m0.w = fmaxf(m0.w, fmaf(w0, w4.w, a23.y));
            m1.x = fmaxf(m1.x, fmaf(w1, w4.x, b01.x));
            m1.y = fmaxf(m1.y, fmaf(w1, w4.y, b01.y));
            m1.z = fmaxf(m1.z, fmaf(w1, w4.z, b23.x));
            m1.w = fmaxf(m1.w, fmaf(w1, w4.w, b23.y));
        }
        if (e < end) {
            int2 p0 = __ldg(&g_sorted[e]);
            uint2 u0 = *(const uint2*)(g_Ps16 + (size_t)p0.x * HID + lane * 4);
            float w0 = __int_as_float(p0.y);
            float2 a01 = __half22float2(*(__half2*)&u0.x);
            float2 a23 = __half22float2(*(__half2*)&u0.y);
            m0.x = fmaxf(m0.x, fmaf(w0, w4.x, a01.x));
            m0.y = fmaxf(m0.y, fmaf(w0, w4.y, a01.y));
            m0.z = fmaxf(m0.z, fmaf(w0, w4.z, a23.x));
            m0.w = fmaxf(m0.w, fmaf(w0, w4.w, a23.y));
        }
        m0.x = fmaxf(m0.x, m1.x); m0.y = fmaxf(m0.y, m1.y);
        m0.z = fmaxf(m0.z, m1.z); m0.w = fmaxf(m0.w, m1.w);

        float4 q = *(const float4*)(g_P + (size_t)gw * PW + lane * 4);  // z@Wd
        float4 b = *(const float4*)(bm + lane * 4);
        outv.x = q.x + b.x + m0.x;
        outv.y = q.y + b.y + m0.y;
        outv.z = q.z + b.z + m0.z;
        outv.w = q.w + b.w + m0.w;
    }
    *(float4*)(g_agg + (size_t)gw * HID + lane * 4) = outv;
}

// ---------------- launch ----------------
extern "C" void kernel_launch(void* const* d_in, const int* in_sizes, int n_in,
                              void* d_out, int out_size) {
    const float* z    = (const float*)d_in[0];
    const float* ew   = (const float*)d_in[1];
    const int*   esrc = (const int*)d_in[2];
    const int*   edst = (const int*)d_in[3];
    const float* Wm   = (const float*)d_in[4];
    const float* bm   = (const float*)d_in[5];
    const float* W1   = (const float*)d_in[6];
    const float* b1   = (const float*)d_in[7];
    const float* W2   = (const float*)d_in[8];
    const float* b2   = (const float*)d_in[9];
    float* out = (float*)d_out;

    static int prep_blocks = 0;
    static bool init_done = false;
    if (!init_done) {
        cudaFuncSetAttribute(gemm_z,    cudaFuncAttributeMaxDynamicSharedMemorySize, SM_TOTAL);
        cudaFuncSetAttribute(gemm_tail, cudaFuncAttributeMaxDynamicSharedMemorySize, SM_T_TOTAL);
        int nb = 0, nsm = 0;
        cudaOccupancyMaxActiveBlocksPerMultiprocessor(&nb, prep_kernel, 256, 0);
        cudaDeviceGetAttribute(&nsm, cudaDevAttrMultiProcessorCount, 0);
        prep_blocks = nb * nsm;
        if (prep_blocks < SCAN_BLOCKS) prep_blocks = SCAN_BLOCKS;
        init_done = true;
    }

    const int NT = (N_NODES + 127) / 128;  // 391 row tiles

    // 1. fused prep: weight split + edge counting sort (cooperative)
    {
        void* args[6] = { (void*)&esrc, (void*)&edst, (void*)&ew,
                          (void*)&Wm, (void*)&W1, (void*)&W2 };
        cudaLaunchCooperativeKernel((void*)prep_kernel, dim3(prep_blocks), dim3(256), args, 0, 0);
    }

    // 2. z GEMMs: by0 -> fp16 z@Ws table; by1 -> z@Wd; by2 -> z@W1a
    gemm_z<<<dim3(NT, 3), 256, SM_TOTAL>>>(z, N_NODES);

    // 3. aggregation
    agg_kernel<<<(N_NODES * 32 + 255) / 256, 256>>>(Wm, bm);

    // 4. fused tail: out = relu(agg@W1b + P3 + b1) @ W2 + b2
    gemm_tail<<<NT, 256, SM_T_TOTAL>>>(b1, b2, out, N_NODES);
}

// round 13
// speedup vs baseline: 1.0602x; 1.0048x over previous
#include <cuda_runtime.h>
#include <cuda_bf16.h>
#include <cuda_fp16.h>
#include <cooperative_groups.h>
#include <math_constants.h>
#include <cstdint>

namespace cg = cooperative_groups;

#define N_NODES 50000
#define N_EDGES 800000
#define HID 128
#define PW 256   // [0:128)=z@Wd, [128:256)=z@W1a
#define SCAN_BLOCKS ((N_NODES + 255) / 256)   // 196
#define NTHREADS 512

// ---------------- scratch ----------------
__device__ float  g_P[(size_t)N_NODES * PW];
__device__ __half g_Ps16[(size_t)N_NODES * HID];   // fp16 z@Ws for edge gather
__device__ float  g_agg[(size_t)N_NODES * HID];
__device__ int    g_count[N_NODES];
__device__ int    g_offset[N_NODES];
__device__ int    g_cursor[N_NODES];
__device__ int    g_blocksum[SCAN_BLOCKS];
__device__ int2   g_sorted[N_EDGES];               // (src, w bits)
// pre-split, pre-swizzled weights: 0=Ws 1=Wd 2=W1a 3=W1b 4=W2
__device__ __nv_bfloat16 g_WH[5][16384];
__device__ __nv_bfloat16 g_WL[5][16384];

// ---------------- mma.sync helpers (portable sm_80+ PTX) ----------------
__device__ __forceinline__ uint32_t smem_u32(const void* p) {
    uint32_t a;
    asm("{ .reg .u64 t; cvta.to.shared.u64 t, %1; cvt.u32.u64 %0, t; }" : "=r"(a) : "l"(p));
    return a;
}
__device__ __forceinline__ void ldsm_x4(uint32_t* r, uint32_t addr) {
    asm volatile("ldmatrix.sync.aligned.m8n8.x4.shared.b16 {%0,%1,%2,%3}, [%4];"
                 : "=r"(r[0]), "=r"(r[1]), "=r"(r[2]), "=r"(r[3]) : "r"(addr));
}
__device__ __forceinline__ void ldsm_x4_t(uint32_t* r, uint32_t addr) {
    asm volatile("ldmatrix.sync.aligned.m8n8.x4.trans.shared.b16 {%0,%1,%2,%3}, [%4];"
                 : "=r"(r[0]), "=r"(r[1]), "=r"(r[2]), "=r"(r[3]) : "r"(addr));
}
__device__ __forceinline__ void mma16816(float* c, const uint32_t* a, const uint32_t* b) {
    asm volatile(
        "mma.sync.aligned.m16n8k16.row.col.f32.bf16.bf16.f32 "
        "{%0,%1,%2,%3}, {%4,%5,%6,%7}, {%8,%9}, {%0,%1,%2,%3};"
        : "+f"(c[0]), "+f"(c[1]), "+f"(c[2]), "+f"(c[3])
        : "r"(a[0]), "r"(a[1]), "r"(a[2]), "r"(a[3]), "r"(b[0]), "r"(b[1]));
}
__device__ __forceinline__ uint32_t pack2(float x, float y) {
    __nv_bfloat162 h = __floats2bfloat162_rn(x, y);
    return *(uint32_t*)&h;
}
__device__ __forceinline__ float tobf(float x) {
    return __bfloat162float(__float2bfloat16(x));
}
// swizzled byte offset inside a [128][128] bf16 tile (256B rows)
__device__ __forceinline__ uint32_t swz(int row, int col) {
    return (uint32_t)(row * 256 + ((((col >> 3) ^ (row & 7))) << 4) + (col & 7) * 2);
}

// smem plan
#define SM_AHI 0
#define SM_ALO 32768
#define SM_BHI 65536
#define SM_BLO 98304
#define SM_TOTAL 131072
#define SM_B2H 131072
#define SM_B2L 163840
#define SM_T_TOTAL 196608

// ---- building blocks (512 threads) ----
__device__ __forceinline__ void conv_A(const float* __restrict__ A, int bm0, int M,
                                       char* smem, int tid) {
#pragma unroll
    for (int i = 0; i < 16; i++) {
        int p = tid + i * NTHREADS;
        int row = p >> 6, col = (p & 63) * 2;
        float2 v = make_float2(0.f, 0.f);
        int gr = bm0 + row;
        if (gr < M) v = *(const float2*)(A + (size_t)gr * 128 + col);
        float hx = tobf(v.x), hy = tobf(v.y);
        uint32_t off = swz(row, col);
        *(uint32_t*)(smem + SM_AHI + off) = pack2(hx, hy);
        *(uint32_t*)(smem + SM_ALO + off) = pack2(v.x - hx, v.y - hy);
    }
}
__device__ __forceinline__ void copy_B(int m, char* smem, int offH, int offL, int tid) {
    const uint4* __restrict__ sh = (const uint4*)g_WH[m];
    const uint4* __restrict__ sl = (const uint4*)g_WL[m];
    uint4* dh = (uint4*)(smem + offH);
    uint4* dl = (uint4*)(smem + offL);
#pragma unroll
    for (int i = 0; i < 4; i++) {
        dh[tid + i * NTHREADS] = sh[tid + i * NTHREADS];
        dl[tid + i * NTHREADS] = sl[tid + i * NTHREADS];
    }
}
// 16-warp tiling: warp (wm, wn) -> rows wm*32..+31, cols wn*32..+31
__device__ __forceinline__ void mma_stage(uint32_t sb, int bHo, int bLo,
                                          int wm, int wn, int lane, float (&acc)[2][4][4]) {
    const int sub = lane >> 3;
    const int l7 = lane & 7;
    const int radd = (sub & 1) * 8;
    const int cadd = (sub >> 1) * 8;
#pragma unroll
    for (int ks = 0; ks < 8; ks++) {
        const int k0 = ks * 16;
        uint32_t aH[2][4], aL[2][4], bH[2][4], bL[2][4];
#pragma unroll
        for (int mt = 0; mt < 2; mt++) {
            uint32_t o = swz(wm * 32 + mt * 16 + l7 + radd, k0 + cadd);
            ldsm_x4(aH[mt], sb + SM_AHI + o);
            ldsm_x4(aL[mt], sb + SM_ALO + o);
        }
#pragma unroll
        for (int pr = 0; pr < 2; pr++) {
            uint32_t o = swz(k0 + l7 + radd, wn * 32 + pr * 16 + cadd);
            ldsm_x4_t(bH[pr], sb + bHo + o);
            ldsm_x4_t(bL[pr], sb + bLo + o);
        }
#pragma unroll
        for (int mt = 0; mt < 2; mt++)
#pragma unroll
            for (int nt = 0; nt < 4; nt++) {
                const uint32_t* bh = &bH[nt >> 1][(nt & 1) * 2];
                const uint32_t* bl = &bL[nt >> 1][(nt & 1) * 2];
                mma16816(acc[mt][nt], aH[mt], bh);
                mma16816(acc[mt][nt], aH[mt], bl);
                mma16816(acc[mt][nt], aL[mt], bh);
            }
    }
}

// ---------------- GEMM over z: by=0 -> z@Ws (fp16 table); by=1 -> z@Wd; by=2 -> z@W1a
__global__ __launch_bounds__(NTHREADS)
void gemm_z(const float* __restrict__ z, int M)
{
    extern __shared__ char smem[];
    const uint32_t sb = smem_u32(smem);
    const int tid = threadIdx.x;
    const int wid = tid >> 5;
    const int lane = tid & 31;
    const int bm0 = blockIdx.x * 128;
    const int by = blockIdx.y;

    conv_A(z, bm0, M, smem, tid);
    copy_B(by, smem, SM_BHI, SM_BLO, tid);
    __syncthreads();

    const int wm = wid & 3, wn = wid >> 2;
    float acc[2][4][4];
#pragma unroll
    for (int mt = 0; mt < 2; mt++)
#pragma unroll
        for (int nt = 0; nt < 4; nt++)
#pragma unroll
            for (int j = 0; j < 4; j++) acc[mt][nt][j] = 0.f;

    mma_stage(sb, SM_BHI, SM_BLO, wm, wn, lane, acc);

    const int g = lane >> 2, tg = lane & 3;
#pragma unroll
    for (int mt = 0; mt < 2; mt++)
#pragma unroll
        for (int half = 0; half < 2; half++) {
            int r = bm0 + wm * 32 + mt * 16 + g + half * 8;
            if (r >= M) continue;
#pragma unroll
            for (int nt = 0; nt < 4; nt++) {
                int lc = wn * 32 + nt * 8 + 2 * tg;
                float vx = acc[mt][nt][half * 2 + 0];
                float vy = acc[mt][nt][half * 2 + 1];
                if (by == 0) {
                    *(__half2*)(g_Ps16 + (size_t)r * HID + lc) = __floats2half2_rn(vx, vy);
                } else {
                    float* orow = g_P + (size_t)r * PW + (by - 1) * 128;
                    *(float2*)(orow + lc) = make_float2(vx, vy);
                }
            }
        }
}

// ---------------- fused tail: out = relu(agg@W1b + P[:,128:256) + b1) @ W2 + b2 ----------------
__global__ __launch_bounds__(NTHREADS)
void gemm_tail(const float* __restrict__ b1, const float* __restrict__ b2,
               float* __restrict__ out, int M)
{
    extern __shared__ char smem[];
    const uint32_t sb = smem_u32(smem);
    const int tid = threadIdx.x;
    const int wid = tid >> 5;
    const int lane = tid & 31;
    const int bm0 = blockIdx.x * 128;
    const int wm = wid & 3, wn = wid >> 2;
    const int g = lane >> 2, tg = lane & 3;

    conv_A(g_agg, bm0, M, smem, tid);
    copy_B(3, smem, SM_BHI, SM_BLO, tid);   // W1b
    copy_B(4, smem, SM_B2H, SM_B2L, tid);   // W2
    __syncthreads();

    float acc[2][4][4];
#pragma unroll
    for (int mt = 0; mt < 2; mt++)
#pragma unroll
        for (int nt = 0; nt < 4; nt++)
#pragma unroll
            for (int j = 0; j < 4; j++) acc[mt][nt][j] = 0.f;

    mma_stage(sb, SM_BHI, SM_BLO, wm, wn, lane, acc);
    __syncthreads();   // all reads of A smem done before overwrite

    // hidden = relu(acc + b1 + P[:,128:256)) -> split bf16 back into A smem
#pragma unroll
    for (int mt = 0; mt < 2; mt++)
#pragma unroll
        for (int half = 0; half < 2; half++) {
            int lr = wm * 32 + mt * 16 + g + half * 8;
            int r = bm0 + lr;
            const float* crow = (r < M) ? (g_P + (size_t)r * PW + 128) : nullptr;
#pragma unroll
            for (int nt = 0; nt < 4; nt++) {
                int lc = wn * 32 + nt * 8 + 2 * tg;
                float vx = acc[mt][nt][half * 2 + 0] + b1[lc];
                float vy = acc[mt][nt][half * 2 + 1] + b1[lc + 1];
                if (crow) { vx += crow[lc]; vy += crow[lc + 1]; }
                vx = fmaxf(vx, 0.f); vy = fmaxf(vy, 0.f);
                float hx = tobf(vx), hy = tobf(vy);
                uint32_t off = swz(lr, lc);
                *(uint32_t*)(smem + SM_AHI + off) = pack2(hx, hy);
                *(uint32_t*)(smem + SM_ALO + off) = pack2(vx - hx, vy - hy);
            }
        }
    __syncthreads();

#pragma unroll
    for (int mt = 0; mt < 2; mt++)
#pragma unroll
        for (int nt = 0; nt < 4; nt++)
#pragma unroll
            for (int j = 0; j < 4; j++) acc[mt][nt][j] = 0.f;

    mma_stage(sb, SM_B2H, SM_B2L, wm, wn, lane, acc);

#pragma unroll
    for (int mt = 0; mt < 2; mt++)
#pragma unroll
        for (int half = 0; half < 2; half++) {
            int r = bm0 + wm * 32 + mt * 16 + g + half * 8;
            if (r >= M) continue;
            float* orow = out + (size_t)r * HID;
#pragma unroll
            for (int nt = 0; nt < 4; nt++) {
                int lc = wn * 32 + nt * 8 + 2 * tg;
                float2 v;
                v.x = acc[mt][nt][half * 2 + 0] + b2[lc];
                v.y = acc[mt][nt][half * 2 + 1] + b2[lc + 1];
                *(float2*)(orow + lc) = v;
            }
        }
}

// ---------------- fused prep (cooperative): W-split + zero+hist+scan+scatter ----------------
__global__ void prep_kernel(const int* __restrict__ esrc, const int* __restrict__ edst,
                            const float* __restrict__ ew,
                            const float* __restrict__ Wm, const float* __restrict__ W1,
                            const float* __restrict__ W2)
{
    cg::grid_group grid = cg::this_grid();
    const int bid = blockIdx.x, t = threadIdx.x;
    const int gt = bid * 256 + t;
    const int gsz = gridDim.x * 256;

    // phase -1: split+swizzle the 5 weight matrices
    for (int idx = gt; idx < 5 * 16384; idx += gsz) {
        int m = idx >> 14;
        int p = idx & 16383;
        int row = p >> 7, col = p & 127;
        const float* src = (m == 0) ? (Wm + 128 * 128)
                         : (m == 1) ? Wm
                         : (m == 2) ? W1
                         : (m == 3) ? (W1 + 128 * 128) : W2;
        float v = src[row * 128 + col];
        float h = tobf(v);
        uint32_t off = swz(row, col);   // byte offset
        *(__nv_bfloat16*)((char*)g_WH[m] + off) = __float2bfloat16(h);
        *(__nv_bfloat16*)((char*)g_WL[m] + off) = __float2bfloat16(v - h);
    }

    // phase 0: zero counts
    for (int i = gt; i < N_NODES; i += gsz) g_count[i] = 0;
    grid.sync();

    // phase 1: histogram
    for (int i = gt; i < N_EDGES; i += gsz) atomicAdd(&g_count[edst[i]], 1);
    grid.sync();

    // phase 2: block-local scan
    __shared__ int ws[8];
    if (bid < SCAN_BLOCKS) {
        int i = bid * 256 + t;
        int v = (i < N_NODES) ? g_count[i] : 0;
        int lane = t & 31, w = t >> 5;
        int incl = v;
#pragma unroll
        for (int o = 1; o < 32; o <<= 1) {
            int y = __shfl_up_sync(0xffffffffu, incl, o);
            if (lane >= o) incl += y;
        }
        if (lane == 31) ws[w] = incl;
        __syncthreads();
        if (t < 8) {
            int x = ws[t];
#pragma unroll
            for (int o = 1; o < 8; o <<= 1) {
                int y = __shfl_up_sync(0xffu, x, o, 8);
                if (t >= o) x += y;
            }
            ws[t] = x;
        }
        __syncthreads();
        int excl = incl - v + (w > 0 ? ws[w - 1] : 0);
        if (i < N_NODES) g_offset[i] = excl;
        if (t == 255) g_blocksum[bid] = ws[7];
    }
    grid.sync();

    // phase 3: scan block sums
    if (bid == 0) {
        int v = (t < SCAN_BLOCKS) ? g_blocksum[t] : 0;
        int lane = t & 31, w = t >> 5;
        int incl = v;
#pragma unroll
        for (int o = 1; o < 32; o <<= 1) {
            int y = __shfl_up_sync(0xffffffffu, incl, o);
            if (lane >= o) incl += y;
        }
        if (lane == 31) ws[w] = incl;
        __syncthreads();
        if (t < 8) {
            int x = ws[t];
#pragma unroll
            for (int o = 1; o < 8; o <<= 1) {
                int y = __shfl_up_sync(0xffu, x, o, 8);
                if (t >= o) x += y;
            }
            ws[t] = x;
        }
        __syncthreads();
        int excl = incl - v + (w > 0 ? ws[w - 1] : 0);
        if (t < SCAN_BLOCKS) g_blocksum[t] = excl;
    }
    grid.sync();

    // phase 4: add block offsets, init cursor
    if (bid < SCAN_BLOCKS) {
        int i = bid * 256 + t;
        if (i < N_NODES) {
            int off = g_offset[i] + g_blocksum[bid];
            g_offset[i] = off;
            g_cursor[i] = off;
        }
    }
    grid.sync();

    // phase 5: scatter
    for (int i = gt; i < N_EDGES; i += gsz) {
        int d = edst[i];
        int pos = atomicAdd(&g_cursor[d], 1);
        g_sorted[pos] = make_int2(esrc[i], __float_as_int(ew[i]));
    }
}

// ---------------- per-node max aggregation (fp16 table, 2-way ILP) ----------------
__global__ void agg_kernel(const float* __restrict__ Wm, const float* __restrict__ bm) {
    int gw = (blockIdx.x * blockDim.x + threadIdx.x) >> 5;
    int lane = threadIdx.x & 31;
    if (gw >= N_NODES) return;

    int start = g_offset[gw];
    int end = (gw + 1 < N_NODES ? g_offset[gw + 1] : N_EDGES);
    float4 outv = make_float4(0.f, 0.f, 0.f, 0.f);
    if (end > start) {
        float4 w4 = *(const float4*)(Wm + 256 * 128 + lane * 4);  // ww
        const float NI = -CUDART_INF_F;
        float4 m0 = make_float4(NI, NI, NI, NI);
        float4 m1 = make_float4(NI, NI, NI, NI);
        int e = start;
        for (; e + 2 <= end; e += 2) {
            int2 p0 = __ldg(&g_sorted[e]);
            int2 p1 = __ldg(&g_sorted[e + 1]);
            uint2 u0 = *(const uint2*)(g_Ps16 + (size_t)p0.x * HID + lane * 4);
            uint2 u1 = *(const uint2*)(g_Ps16 + (size_t)p1.x * HID + lane * 4);
            float w0 = __int_as_float(p0.y);
            float w1 = __int_as_float(p1.y);
            float2 a01 = __half22float2(*(__half2*)&u0.x);
            float2 a23 = __half22float2(*(__half2*)&u0.y);
            float2 b01 = __half22float2(*(__half2*)&u1.x);
            float2 b23 = __half22float2(*(__half2*)&u1.y);
            m0.x = fmaxf(m0.x, fmaf(w0, w4.x, a01.x));
            m0.y = fmaxf(m0.y, fmaf(w0, w4.y, a01.y));
            m0.z = fmaxf(m0.z, fmaf(w0, w4.z, a23.x));
            m0.w = fmaxf(m0.w, fmaf(w0, w4.w, a23.y));
            m1.x = fmaxf(m1.x, fmaf(w1, w4.x, b01.x));
            m1.y = fmaxf(m1.y, fmaf(w1, w4.y, b01.y));
            m1.z = fmaxf(m1.z, fmaf(w1, w4.z, b23.x));
            m1.w = fmaxf(m1.w, fmaf(w1, w4.w, b23.y));
        }
        if (e < end) {
            int2 p0 = __ldg(&g_sorted[e]);
            uint2 u0 = *(const uint2*)(g_Ps16 + (size_t)p0.x * HID + lane * 4);
            float w0 = __int_as_float(p0.y);
            float2 a01 = __half22float2(*(__half2*)&u0.x);
            float2 a23 = __half22float2(*(__half2*)&u0.y);
            m0.x = fmaxf(m0.x, fmaf(w0, w4.x, a01.x));
            m0.y = fmaxf(m0.y, fmaf(w0, w4.y, a01.y));
            m0.z = fmaxf(m0.z, fmaf(w0, w4.z, a23.x));
            m0.w = fmaxf(m0.w, fmaf(w0, w4.w, a23.y));
        }
        m0.x = fmaxf(m0.x, m1.x); m0.y = fmaxf(m0.y, m1.y);
        m0.z = fmaxf(m0.z, m1.z); m0.w = fmaxf(m0.w, m1.w);

        float4 q = *(const float4*)(g_P + (size_t)gw * PW + lane * 4);  // z@Wd
        float4 b = *(const float4*)(bm + lane * 4);
        outv.x = q.x + b.x + m0.x;
        outv.y = q.y + b.y + m0.y;
        outv.z = q.z + b.z + m0.z;
        outv.w = q.w + b.w + m0.w;
    }
    *(float4*)(g_agg + (size_t)gw * HID + lane * 4) = outv;
}

// ---------------- launch ----------------
extern "C" void kernel_launch(void* const* d_in, const int* in_sizes, int n_in,
                              void* d_out, int out_size) {
    const float* z    = (const float*)d_in[0];
    const float* ew   = (const float*)d_in[1];
    const int*   esrc = (const int*)d_in[2];
    const int*   edst = (const int*)d_in[3];
    const float* Wm   = (const float*)d_in[4];
    const float* bm   = (const float*)d_in[5];
    const float* W1   = (const float*)d_in[6];
    const float* b1   = (const float*)d_in[7];
    const float* W2   = (const float*)d_in[8];
    const float* b2   = (const float*)d_in[9];
    float* out = (float*)d_out;

    static int prep_blocks = 0;
    static bool init_done = false;
    if (!init_done) {
        cudaFuncSetAttribute(gemm_z,    cudaFuncAttributeMaxDynamicSharedMemorySize, SM_TOTAL);
        cudaFuncSetAttribute(gemm_tail, cudaFuncAttributeMaxDynamicSharedMemorySize, SM_T_TOTAL);
        int nb = 0, nsm = 0;
        cudaOccupancyMaxActiveBlocksPerMultiprocessor(&nb, prep_kernel, 256, 0);
        cudaDeviceGetAttribute(&nsm, cudaDevAttrMultiProcessorCount, 0);
        prep_blocks = nb * nsm;
        if (prep_blocks < SCAN_BLOCKS) prep_blocks = SCAN_BLOCKS;
        init_done = true;
    }

    const int NT = (N_NODES + 127) / 128;  // 391 row tiles

    // 1. fused prep: weight split + edge counting sort (cooperative)
    {
        void* args[6] = { (void*)&esrc, (void*)&edst, (void*)&ew,
                          (void*)&Wm, (void*)&W1, (void*)&W2 };
        cudaLaunchCooperativeKernel((void*)prep_kernel, dim3(prep_blocks), dim3(256), args, 0, 0);
    }

    // 2. z GEMMs: by0 -> fp16 z@Ws table; by1 -> z@Wd; by2 -> z@W1a
    gemm_z<<<dim3(NT, 3), NTHREADS, SM_TOTAL>>>(z, N_NODES);

    // 3. aggregation
    agg_kernel<<<(N_NODES * 32 + 255) / 256, 256>>>(Wm, bm);

    // 4. fused tail: out = relu(agg@W1b + P3 + b1) @ W2 + b2
    gemm_tail<<<NT, NTHREADS, SM_T_TOTAL>>>(b1, b2, out, N_NODES);
}

// round 15
// speedup vs baseline: 1.0965x; 1.0342x over previous
#include <cuda_runtime.h>
#include <cuda_bf16.h>
#include <cuda_fp16.h>
#include <cooperative_groups.h>
#include <math_constants.h>
#include <cstdint>

namespace cg = cooperative_groups;

#define N_NODES 50000
#define N_EDGES 800000
#define HID 128
#define NTILES ((N_NODES + 127) / 128)        // 391
#define SCAN_BLOCKS ((N_NODES + 255) / 256)   // 196
#define NTHREADS 512

// ---------------- scratch ----------------
__device__ float  g_P[(size_t)N_NODES * HID];      // z @ Wz (fp32)
__device__ __half g_Ps16[(size_t)N_NODES * HID];   // fp16 z@Ws for edge gather
__device__ int    g_count[N_NODES];
__device__ int    g_offset[N_NODES];
__device__ int    g_cursor[N_NODES];
__device__ int    g_blocksum[SCAN_BLOCKS];
__device__ int2   g_sorted[N_EDGES];               // (src, w bits)
// pre-split, pre-swizzled weights: 0=Ws 1=Wz 2=W1b 3=W2
__device__ __nv_bfloat16 g_WH[4][16384];
__device__ __nv_bfloat16 g_WL[4][16384];
// pre-split, pre-swizzled A operands (per-tile 32KB blobs)
__device__ __nv_bfloat16 g_zH[(size_t)NTILES * 16384];
__device__ __nv_bfloat16 g_zL[(size_t)NTILES * 16384];
__device__ __nv_bfloat16 g_aggH[(size_t)NTILES * 16384];
__device__ __nv_bfloat16 g_aggL[(size_t)NTILES * 16384];

// ---------------- mma.sync helpers (portable sm_80+ PTX) ----------------
__device__ __forceinline__ uint32_t smem_u32(const void* p) {
    uint32_t a;
    asm("{ .reg .u64 t; cvta.to.shared.u64 t, %1; cvt.u32.u64 %0, t; }" : "=r"(a) : "l"(p));
    return a;
}
__device__ __forceinline__ void ldsm_x4(uint32_t* r, uint32_t addr) {
    asm volatile("ldmatrix.sync.aligned.m8n8.x4.shared.b16 {%0,%1,%2,%3}, [%4];"
                 : "=r"(r[0]), "=r"(r[1]), "=r"(r[2]), "=r"(r[3]) : "r"(addr));
}
__device__ __forceinline__ void ldsm_x4_t(uint32_t* r, uint32_t addr) {
    asm volatile("ldmatrix.sync.aligned.m8n8.x4.trans.shared.b16 {%0,%1,%2,%3}, [%4];"
                 : "=r"(r[0]), "=r"(r[1]), "=r"(r[2]), "=r"(r[3]) : "r"(addr));
}
__device__ __forceinline__ void mma16816(float* c, const uint32_t* a, const uint32_t* b) {
    asm volatile(
        "mma.sync.aligned.m16n8k16.row.col.f32.bf16.bf16.f32 "
        "{%0,%1,%2,%3}, {%4,%5,%6,%7}, {%8,%9}, {%0,%1,%2,%3};"
        : "+f"(c[0]), "+f"(c[1]), "+f"(c[2]), "+f"(c[3])
        : "r"(a[0]), "r"(a[1]), "r"(a[2]), "r"(a[3]), "r"(b[0]), "r"(b[1]));
}
__device__ __forceinline__ uint32_t pack2(float x, float y) {
    __nv_bfloat162 h = __floats2bfloat162_rn(x, y);
    return *(uint32_t*)&h;
}
__device__ __forceinline__ float tobf(float x) {
    return __bfloat162float(__float2bfloat16(x));
}
// swizzled byte offset inside a [128][128] bf16 tile (256B rows)
__device__ __forceinline__ uint32_t swz(int row, int col) {
    return (uint32_t)(row * 256 + ((((col >> 3) ^ (row & 7))) << 4) + (col & 7) * 2);
}

// smem plan
#define SM_AHI 0
#define SM_ALO 32768
#define SM_BHI 65536
#define SM_BLO 98304
#define SM_TOTAL 131072
#define SM_B2H 131072
#define SM_B2L 163840
#define SM_T_TOTAL 196608

// ---- building blocks (512 threads) ----
__device__ __forceinline__ void copy_blobA(const __nv_bfloat16* __restrict__ H,
                                           const __nv_bfloat16* __restrict__ L,
                                           char* smem, int tid) {
    const uint4* sh = (const uint4*)H;
    const uint4* sl = (const uint4*)L;
    uint4* dh = (uint4*)(smem + SM_AHI);
    uint4* dl = (uint4*)(smem + SM_ALO);
#pragma unroll
    for (int i = 0; i < 4; i++) {
        dh[tid + i * NTHREADS] = sh[tid + i * NTHREADS];
        dl[tid + i * NTHREADS] = sl[tid + i * NTHREADS];
    }
}
__device__ __forceinline__ void copy_B(int m, char* smem, int offH, int offL, int tid) {
    const uint4* __restrict__ sh = (const uint4*)g_WH[m];
    const uint4* __restrict__ sl = (const uint4*)g_WL[m];
    uint4* dh = (uint4*)(smem + offH);
    uint4* dl = (uint4*)(smem + offL);
#pragma unroll
    for (int i = 0; i < 4; i++) {
        dh[tid + i * NTHREADS] = sh[tid + i * NTHREADS];
        dl[tid + i * NTHREADS] = sl[tid + i * NTHREADS];
    }
}
// 16-warp tiling: warp (wm, wn) -> rows wm*32..+31, cols wn*32..+31
__device__ __forceinline__ void mma_stage(uint32_t sb, int bHo, int bLo,
                                          int wm, int wn, int lane, float (&acc)[2][4][4]) {
    const int sub = lane >> 3;
    const int l7 = lane & 7;
    const int radd = (sub & 1) * 8;
    const int cadd = (sub >> 1) * 8;
#pragma unroll
    for (int ks = 0; ks < 8; ks++) {
        const int k0 = ks * 16;
        uint32_t aH[2][4], aL[2][4], bH[2][4], bL[2][4];
#pragma unroll
        for (int mt = 0; mt < 2; mt++) {
            uint32_t o = swz(wm * 32 + mt * 16 + l7 + radd, k0 + cadd);
            ldsm_x4(aH[mt], sb + SM_AHI + o);
            ldsm_x4(aL[mt], sb + SM_ALO + o);
        }
#pragma unroll
        for (int pr = 0; pr < 2; pr++) {
            uint32_t o = swz(k0 + l7 + radd, wn * 32 + pr * 16 + cadd);
            ldsm_x4_t(bH[pr], sb + bHo + o);
            ldsm_x4_t(bL[pr], sb + bLo + o);
        }
#pragma unroll
        for (int mt = 0; mt < 2; mt++)
#pragma unroll
            for (int nt = 0; nt < 4; nt++) {
                const uint32_t* bh = &bH[nt >> 1][(nt & 1) * 2];
                const uint32_t* bl = &bL[nt >> 1][(nt & 1) * 2];
                mma16816(acc[mt][nt], aH[mt], bh);
                mma16816(acc[mt][nt], aH[mt], bl);
                mma16816(acc[mt][nt], aL[mt], bh);
            }
    }
}

// ---------------- GEMM over z: by=0 -> z@Ws (fp16 table); by=1 -> z@Wz (fp32 P)
__global__ __launch_bounds__(NTHREADS)
void gemm_z(int M)
{
    extern __shared__ char smem[];
    const uint32_t sb = smem_u32(smem);
    const int tid = threadIdx.x;
    const int wid = tid >> 5;
    const int lane = tid & 31;
    const int tile = blockIdx.x;
    const int bm0 = tile * 128;
    const int by = blockIdx.y;

    copy_blobA(g_zH + (size_t)tile * 16384, g_zL + (size_t)tile * 16384, smem, tid);
    copy_B(by, smem, SM_BHI, SM_BLO, tid);   // 0=Ws, 1=Wz
    __syncthreads();

    const int wm = wid & 3, wn = wid >> 2;
    float acc[2][4][4];
#pragma unroll
    for (int mt = 0; mt < 2; mt++)
#pragma unroll
        for (int nt = 0; nt < 4; nt++)
#pragma unroll
            for (int j = 0; j < 4; j++) acc[mt][nt][j] = 0.f;

    mma_stage(sb, SM_BHI, SM_BLO, wm, wn, lane, acc);

    const int g = lane >> 2, tg = lane & 3;
#pragma unroll
    for (int mt = 0; mt < 2; mt++)
#pragma unroll
        for (int half = 0; half < 2; half++) {
            int r = bm0 + wm * 32 + mt * 16 + g + half * 8;
            if (r >= M) continue;
#pragma unroll
            for (int nt = 0; nt < 4; nt++) {
                int lc = wn * 32 + nt * 8 + 2 * tg;
                float vx = acc[mt][nt][half * 2 + 0];
                float vy = acc[mt][nt][half * 2 + 1];
                if (by == 0) {
                    *(__half2*)(g_Ps16 + (size_t)r * HID + lc) = __floats2half2_rn(vx, vy);
                } else {
                    *(float2*)(g_P + (size_t)r * HID + lc) = make_float2(vx, vy);
                }
            }
        }
}

// ---------------- fused tail: out = relu(aggX@W1b + P + b1) @ W2 + b2 ----------------
__global__ __launch_bounds__(NTHREADS)
void gemm_tail(const float* __restrict__ b1, const float* __restrict__ b2,
               float* __restrict__ out, int M)
{
    extern __shared__ char smem[];
    const uint32_t sb = smem_u32(smem);
    const int tid = threadIdx.x;
    const int wid = tid >> 5;
    const int lane = tid & 31;
    const int tile = blockIdx.x;
    const int bm0 = tile * 128;
    const int wm = wid & 3, wn = wid >> 2;
    const int g = lane >> 2, tg = lane & 3;

    copy_blobA(g_aggH + (size_t)tile * 16384, g_aggL + (size_t)tile * 16384, smem, tid);
    copy_B(2, smem, SM_BHI, SM_BLO, tid);   // W1b
    copy_B(3, smem, SM_B2H, SM_B2L, tid);   // W2
    __syncthreads();

    float acc[2][4][4];
#pragma unroll
    for (int mt = 0; mt < 2; mt++)
#pragma unroll
        for (int nt = 0; nt < 4; nt++)
#pragma unroll
            for (int j = 0; j < 4; j++) acc[mt][nt][j] = 0.f;

    mma_stage(sb, SM_BHI, SM_BLO, wm, wn, lane, acc);
    __syncthreads();   // all reads of A smem done before overwrite

    // hidden = relu(acc + b1 + P) -> split bf16 back into A smem
#pragma unroll
    for (int mt = 0; mt < 2; mt++)
#pragma unroll
        for (int half = 0; half < 2; half++) {
            int lr = wm * 32 + mt * 16 + g + half * 8;
            int r = bm0 + lr;
            const float* crow = (r < M) ? (g_P + (size_t)r * HID) : nullptr;
#pragma unroll
            for (int nt = 0; nt < 4; nt++) {
                int lc = wn * 32 + nt * 8 + 2 * tg;
                float vx = acc[mt][nt][half * 2 + 0] + b1[lc];
                float vy = acc[mt][nt][half * 2 + 1] + b1[lc + 1];
                if (crow) { vx += crow[lc]; vy += crow[lc + 1]; }
                vx = fmaxf(vx, 0.f); vy = fmaxf(vy, 0.f);
                float hx = tobf(vx), hy = tobf(vy);
                uint32_t off = swz(lr, lc);
                *(uint32_t*)(smem + SM_AHI + off) = pack2(hx, hy);
                *(uint32_t*)(smem + SM_ALO + off) = pack2(vx - hx, vy - hy);
            }
        }
    __syncthreads();

#pragma unroll
    for (int mt = 0; mt < 2; mt++)
#pragma unroll
        for (int nt = 0; nt < 4; nt++)
#pragma unroll
            for (int j = 0; j < 4; j++) acc[mt][nt][j] = 0.f;

    mma_stage(sb, SM_B2H, SM_B2L, wm, wn, lane, acc);

#pragma unroll
    for (int mt = 0; mt < 2; mt++)
#pragma unroll
        for (int half = 0; half < 2; half++) {
            int r = bm0 + wm * 32 + mt * 16 + g + half * 8;
            if (r >= M) continue;
            float* orow = out + (size_t)r * HID;
#pragma unroll
            for (int nt = 0; nt < 4; nt++) {
                int lc = wn * 32 + nt * 8 + 2 * tg;
                float2 v;
                v.x = acc[mt][nt][half * 2 + 0] + b2[lc];
                v.y = acc[mt][nt][half * 2 + 1] + b2[lc + 1];
                *(float2*)(orow + lc) = v;
            }
        }
}

// ---------------- fused prep (cooperative) ----------------
// phase -1: weight splits (Ws, W1b, W2), Wz = W1a + Wd@W1b, z split; then edge sort.
__global__ void prep_kernel(const int* __restrict__ esrc, const int* __restrict__ edst,
                            const float* __restrict__ ew, const float* __restrict__ z,
                            const float* __restrict__ Wm, const float* __restrict__ W1,
                            const float* __restrict__ W2)
{
    cg::grid_group grid = cg::this_grid();
    const int bid = blockIdx.x, t = threadIdx.x;
    const int gt = bid * 256 + t;
    const int gsz = gridDim.x * 256;

    // weight splits for Ws -> slot0, W1b -> slot2, W2 -> slot3
    for (int idx = gt; idx < 3 * 16384; idx += gsz) {
        int m = idx >> 14;
        int p = idx & 16383;
        int row = p >> 7, col = p & 127;
        const float* src = (m == 0) ? (Wm + 128 * 128)
                         : (m == 1) ? (W1 + 128 * 128) : W2;
        int slot = (m == 0) ? 0 : (m == 1) ? 2 : 3;
        float v = src[row * 128 + col];
        float h = tobf(v);
        uint32_t off = swz(row, col);
        *(__nv_bfloat16*)((char*)g_WH[slot] + off) = __float2bfloat16(h);
        *(__nv_bfloat16*)((char*)g_WL[slot] + off) = __float2bfloat16(v - h);
    }
    // Wz = W1a + Wd @ W1b  -> slot1
    for (int idx = gt; idx < 16384; idx += gsz) {
        int row = idx >> 7, col = idx & 127;
        float acc = W1[row * 128 + col];                 // W1a
        const float* wd = Wm + row * 128;                // Wd row
        const float* w1b = W1 + 128 * 128 + col;         // W1b col
#pragma unroll 8
        for (int k = 0; k < 128; k++) acc += wd[k] * w1b[k * 128];
        float h = tobf(acc);
        uint32_t off = swz(row, col);
        *(__nv_bfloat16*)((char*)g_WH[1] + off) = __float2bfloat16(h);
        *(__nv_bfloat16*)((char*)g_WL[1] + off) = __float2bfloat16(acc - h);
    }
    // z split into per-tile swizzled blobs (pairs)
    for (int idx = gt; idx < NTILES * 8192; idx += gsz) {
        int tile = idx >> 13;
        int p = idx & 8191;
        int row = p >> 6, col = (p & 63) * 2;
        int gr = tile * 128 + row;
        float2 v = make_float2(0.f, 0.f);
        if (gr < N_NODES) v = *(const float2*)(z + (size_t)gr * 128 + col);
        float hx = tobf(v.x), hy = tobf(v.y);
        uint32_t off = (uint32_t)tile * 32768u + swz(row, col);
        *(uint32_t*)((char*)g_zH + off) = pack2(hx, hy);
        *(uint32_t*)((char*)g_zL + off) = pack2(v.x - hx, v.y - hy);
    }
    // zero counts
    for (int i = gt; i < N_NODES; i += gsz) g_count[i] = 0;
    grid.sync();

    // histogram
    for (int i = gt; i < N_EDGES; i += gsz) atomicAdd(&g_count[edst[i]], 1);
    grid.sync();

    // block-local scan
    __shared__ int ws[8];
    if (bid < SCAN_BLOCKS) {
        int i = bid * 256 + t;
        int v = (i < N_NODES) ? g_count[i] : 0;
        int lane = t & 31, w = t >> 5;
        int incl = v;
#pragma unroll
        for (int o = 1; o < 32; o <<= 1) {
            int y = __shfl_up_sync(0xffffffffu, incl, o);
            if (lane >= o) incl += y;
        }
        if (lane == 31) ws[w] = incl;
        __syncthreads();
        if (t < 8) {
            int x = ws[t];
#pragma unroll
            for (int o = 1; o < 8; o <<= 1) {
                int y = __shfl_up_sync(0xffu, x, o, 8);
                if (t >= o) x += y;
            }
            ws[t] = x;
        }
        __syncthreads();
        int excl = incl - v + (w > 0 ? ws[w - 1] : 0);
        if (i < N_NODES) g_offset[i] = excl;
        if (t == 255) g_blocksum[bid] = ws[7];
    }
    grid.sync();

    // scan block sums
    if (bid == 0) {
        int v = (t < SCAN_BLOCKS) ? g_blocksum[t] : 0;
        int lane = t & 31, w = t >> 5;
        int incl = v;
#pragma unroll
        for (int o = 1; o < 32; o <<= 1) {
            int y = __shfl_up_sync(0xffffffffu, incl, o);
            if (lane >= o) incl += y;
        }
        if (lane == 31) ws[w] = incl;
        __syncthreads();
        if (t < 8) {
            int x = ws[t];
#pragma unroll
            for (int o = 1; o < 8; o <<= 1) {
                int y = __shfl_up_sync(0xffu, x, o, 8);
                if (t >= o) x += y;
            }
            ws[t] = x;
        }
        __syncthreads();
        int excl = incl - v + (w > 0 ? ws[w - 1] : 0);
        if (t < SCAN_BLOCKS) g_blocksum[t] = excl;
    }
    grid.sync();

    // add block offsets, init cursor
    if (bid < SCAN_BLOCKS) {
        int i = bid * 256 + t;
        if (i < N_NODES) {
            int off = g_offset[i] + g_blocksum[bid];
            g_offset[i] = off;
            g_cursor[i] = off;
        }
    }
    grid.sync();

    // scatter
    for (int i = gt; i < N_EDGES; i += gsz) {
        int d = edst[i];
        int pos = atomicAdd(&g_cursor[d], 1);
        g_sorted[pos] = make_int2(esrc[i], __float_as_int(ew[i]));
    }
}

// ---------------- aggregation: writes (bm + mx) as split-bf16 swizzled blobs ----------------
// deg==0 node: row = -(z@Wd) so that row@W1b cancels the folded q@W1b term.
__global__ void agg_kernel(const float* __restrict__ Wm, const float* __restrict__ bm,
                           const float* __restrict__ z) {
    int gw = (blockIdx.x * blockDim.x + threadIdx.x) >> 5;
    int lane = threadIdx.x & 31;
    const int NPAD = NTILES * 128;   // 50048
    if (gw >= NPAD) return;

    float4 outv = make_float4(0.f, 0.f, 0.f, 0.f);
    if (gw < N_NODES) {
        int start = g_offset[gw];
        int end = (gw + 1 < N_NODES ? g_offset[gw + 1] : N_EDGES);
        if (end > start) {
            float4 w4 = *(const float4*)(Wm + 256 * 128 + lane * 4);  // ww
            const float NI = -CUDART_INF_F;
            float4 m0 = make_float4(NI, NI, NI, NI);
            float4 m1 = make_float4(NI, NI, NI, NI);
            int e = start;
            for (; e + 2 <= end; e += 2) {
                int2 p0 = __ldg(&g_sorted[e]);
                int2 p1 = __ldg(&g_sorted[e + 1]);
                uint2 u0 = *(const uint2*)(g_Ps16 + (size_t)p0.x * HID + lane * 4);
                uint2 u1 = *(const uint2*)(g_Ps16 + (size_t)p1.x * HID + lane * 4);
                float w0 = __int_as_float(p0.y);
                float w1 = __int_as_float(p1.y);
                float2 a01 = __half22float2(*(__half2*)&u0.x);
                float2 a23 = __half22float2(*(__half2*)&u0.y);
                float2 b01 = __half22float2(*(__half2*)&u1.x);
                float2 b23 = __half22float2(*(__half2*)&u1.y);
                m0.x = fmaxf(m0.x, fmaf(w0, w4.x, a01.x));
                m0.y = fmaxf(m0.y, fmaf(w0, w4.y, a01.y));
                m0.z = fmaxf(m0.z, fmaf(w0, w4.z, a23.x));
                m0.w = fmaxf(m0.w, fmaf(w0, w4.w, a23.y));
                m1.x = fmaxf(m1.x, fmaf(w1, w4.x, b01.x));
                m1.y = fmaxf(m1.y, fmaf(w1, w4.y, b01.y));
                m1.z = fmaxf(m1.z, fmaf(w1, w4.z, b23.x));
                m1.w = fmaxf(m1.w, fmaf(w1, w4.w, b23.y));
            }
            if (e < end) {
                int2 p0 = __ldg(&g_sorted[e]);
                uint2 u0 = *(const uint2*)(g_Ps16 + (size_t)p0.x * HID + lane * 4);
                float w0 = __int_as_float(p0.y);
                float2 a01 = __half22float2(*(__half2*)&u0.x);
                float2 a23 = __half22float2(*(__half2*)&u0.y);
                m0.x = fmaxf(m0.x, fmaf(w0, w4.x, a01.x));
                m0.y = fmaxf(m0.y, fmaf(w0, w4.y, a01.y));
                m0.z = fmaxf(m0.z, fmaf(w0, w4.z, a23.x));
                m0.w = fmaxf(m0.w, fmaf(w0, w4.w, a23.y));
            }
            m0.x = fmaxf(m0.x, m1.x); m0.y = fmaxf(m0.y, m1.y);
            m0.z = fmaxf(m0.z, m1.z); m0.w = fmaxf(m0.w, m1.w);

            float4 b = *(const float4*)(bm + lane * 4);
            outv.x = b.x + m0.x;
            outv.y = b.y + m0.y;
            outv.z = b.z + m0.z;
            outv.w = b.w + m0.w;
        } else {
            // deg==0: outv = -(z[gw] @ Wd)[4*lane .. 4*lane+3]
            const float* zr = z + (size_t)gw * 128;
            float s0 = 0.f, s1 = 0.f, s2 = 0.f, s3 = 0.f;
            for (int k = 0; k < 128; k++) {
                float zv = zr[k];
                const float* wd = Wm + k * 128 + lane * 4;
                s0 = fmaf(zv, wd[0], s0);
                s1 = fmaf(zv, wd[1], s1);
                s2 = fmaf(zv, wd[2], s2);
                s3 = fmaf(zv, wd[3], s3);
            }
            outv = make_float4(-s0, -s1, -s2, -s3);
        }
    }
    // write split-bf16 into swizzled tile blob
    int tile = gw >> 7, row = gw & 127, col = lane * 4;
    float h0 = tobf(outv.x), h1 = tobf(outv.y), h2 = tobf(outv.z), h3 = tobf(outv.w);
    uint32_t off = (uint32_t)tile * 32768u + swz(row, col);
    uint2 hv = make_uint2(pack2(h0, h1), pack2(h2, h3));
    uint2 lv = make_uint2(pack2(outv.x - h0, outv.y - h1), pack2(outv.z - h2, outv.w - h3));
    *(uint2*)((char*)g_aggH + off) = hv;
    *(uint2*)((char*)g_aggL + off) = lv;
}

// ---------------- launch ----------------
extern "C" void kernel_launch(void* const* d_in, const int* in_sizes, int n_in,
                              void* d_out, int out_size) {
    const float* z    = (const float*)d_in[0];
    const float* ew   = (const float*)d_in[1];
    const int*   esrc = (const int*)d_in[2];
    const int*   edst = (const int*)d_in[3];
    const float* Wm   = (const float*)d_in[4];
    const float* bm   = (const float*)d_in[5];
    const float* W1   = (const float*)d_in[6];
    const float* b1   = (const float*)d_in[7];
    const float* W2   = (const float*)d_in[8];
    const float* b2   = (const float*)d_in[9];
    float* out = (float*)d_out;

    static int prep_blocks = 0;
    static bool init_done = false;
    if (!init_done) {
        cudaFuncSetAttribute(gemm_z,    cudaFuncAttributeMaxDynamicSharedMemorySize, SM_TOTAL);
        cudaFuncSetAttribute(gemm_tail, cudaFuncAttributeMaxDynamicSharedMemorySize, SM_T_TOTAL);
        int nb = 0, nsm = 0;
        cudaOccupancyMaxActiveBlocksPerMultiprocessor(&nb, prep_kernel, 256, 0);
        cudaDeviceGetAttribute(&nsm, cudaDevAttrMultiProcessorCount, 0);
        prep_blocks = nb * nsm;
        if (prep_blocks < SCAN_BLOCKS) prep_blocks = SCAN_BLOCKS;
        init_done = true;
    }

    // 1. fused prep: weight splits + Wz + z split + edge counting sort (cooperative)
    {
        void* args[7] = { (void*)&esrc, (void*)&edst, (void*)&ew, (void*)&z,
                          (void*)&Wm, (void*)&W1, (void*)&W2 };
        cudaLaunchCooperativeKernel((void*)prep_kernel, dim3(prep_blocks), dim3(256), args, 0, 0);
    }

    // 2. z GEMMs: by0 -> fp16 z@Ws table; by1 -> z@Wz (fp32 P)
    gemm_z<<<dim3(NTILES, 2), NTHREADS, SM_TOTAL>>>(N_NODES);

    // 3. aggregation -> split-bf16 swizzled blobs
    agg_kernel<<<(NTILES * 128 * 32) / 256, 256>>>(Wm, bm, z);

    // 4. fused tail: out = relu(aggX@W1b + P + b1) @ W2 + b2
    gemm_tail<<<NTILES, NTHREADS, SM_T_TOTAL>>>(b1, b2, out, N_NODES);
}

// round 16
// speedup vs baseline: 1.2590x; 1.1482x over previous
#include <cuda_runtime.h>
#include <cuda_bf16.h>
#include <cuda_fp16.h>
#include <cooperative_groups.h>
#include <math_constants.h>
#include <cstdint>

namespace cg = cooperative_groups;

#define N_NODES 50000
#define N_EDGES 800000
#define HID 128
#define NTILES ((N_NODES + 127) / 128)        // 391
#define SCAN_BLOCKS ((N_NODES + 255) / 256)   // 196
#define NTHREADS 512

// ---------------- scratch ----------------
__device__ float  g_P[(size_t)N_NODES * HID];      // z @ Wz (fp32)
__device__ __half g_Ps16[(size_t)N_NODES * HID];   // fp16 z@Ws for edge gather
__device__ int    g_count[N_NODES];
__device__ int    g_offset[N_NODES];
__device__ int    g_cursor[N_NODES];
__device__ int    g_blocksum[SCAN_BLOCKS];
__device__ int2   g_sorted[N_EDGES];               // (src, w bits)
// pre-split (fp16 hi/lo), pre-swizzled weights: 0=Ws 1=Wz 2=W1b 3=W2
__device__ __half g_WH[4][16384];
__device__ __half g_WL[4][16384];
// pre-swizzled fp16 A operands (per-tile 32KB blobs)
__device__ __half g_zA[(size_t)NTILES * 16384];
__device__ __half g_aggA[(size_t)NTILES * 16384];

// ---------------- mma.sync helpers (portable sm_80+ PTX) ----------------
__device__ __forceinline__ uint32_t smem_u32(const void* p) {
    uint32_t a;
    asm("{ .reg .u64 t; cvta.to.shared.u64 t, %1; cvt.u32.u64 %0, t; }" : "=r"(a) : "l"(p));
    return a;
}
__device__ __forceinline__ void ldsm_x4(uint32_t* r, uint32_t addr) {
    asm volatile("ldmatrix.sync.aligned.m8n8.x4.shared.b16 {%0,%1,%2,%3}, [%4];"
                 : "=r"(r[0]), "=r"(r[1]), "=r"(r[2]), "=r"(r[3]) : "r"(addr));
}
__device__ __forceinline__ void ldsm_x4_t(uint32_t* r, uint32_t addr) {
    asm volatile("ldmatrix.sync.aligned.m8n8.x4.trans.shared.b16 {%0,%1,%2,%3}, [%4];"
                 : "=r"(r[0]), "=r"(r[1]), "=r"(r[2]), "=r"(r[3]) : "r"(addr));
}
__device__ __forceinline__ void mma16816(float* c, const uint32_t* a, const uint32_t* b) {
    asm volatile(
        "mma.sync.aligned.m16n8k16.row.col.f32.f16.f16.f32 "
        "{%0,%1,%2,%3}, {%4,%5,%6,%7}, {%8,%9}, {%0,%1,%2,%3};"
        : "+f"(c[0]), "+f"(c[1]), "+f"(c[2]), "+f"(c[3])
        : "r"(a[0]), "r"(a[1]), "r"(a[2]), "r"(a[3]), "r"(b[0]), "r"(b[1]));
}
__device__ __forceinline__ uint32_t pack2h(float x, float y) {
    __half2 h = __floats2half2_rn(x, y);
    return *(uint32_t*)&h;
}
__device__ __forceinline__ float toh(float x) {
    return __half2float(__float2half_rn(x));
}
// swizzled byte offset inside a [128][128] fp16 tile (256B rows)
__device__ __forceinline__ uint32_t swz(int row, int col) {
    return (uint32_t)(row * 256 + ((((col >> 3) ^ (row & 7))) << 4) + (col & 7) * 2);
}

// smem plan
#define SM_A   0
#define SM_BHI 32768
#define SM_BLO 65536
#define SM_TOTAL 98304
#define SM_B2H 98304
#define SM_B2L 131072
#define SM_T_TOTAL 163840

// ---- building blocks (512 threads) ----
__device__ __forceinline__ void copy_blobA(const __half* __restrict__ A, char* smem, int tid) {
    const uint4* sa = (const uint4*)A;
    uint4* da = (uint4*)(smem + SM_A);
#pragma unroll
    for (int i = 0; i < 4; i++) da[tid + i * NTHREADS] = sa[tid + i * NTHREADS];
}
__device__ __forceinline__ void copy_B(int m, char* smem, int offH, int offL, int tid) {
    const uint4* __restrict__ sh = (const uint4*)g_WH[m];
    const uint4* __restrict__ sl = (const uint4*)g_WL[m];
    uint4* dh = (uint4*)(smem + offH);
    uint4* dl = (uint4*)(smem + offL);
#pragma unroll
    for (int i = 0; i < 4; i++) {
        dh[tid + i * NTHREADS] = sh[tid + i * NTHREADS];
        dl[tid + i * NTHREADS] = sl[tid + i * NTHREADS];
    }
}
// 16-warp tiling: warp (wm, wn) -> rows wm*32..+31, cols wn*32..+31
// D = A @ Bh + A @ Bl   (A fp16, B split fp16)
__device__ __forceinline__ void mma_stage(uint32_t sb, int bHo, int bLo,
                                          int wm, int wn, int lane, float (&acc)[2][4][4]) {
    const int sub = lane >> 3;
    const int l7 = lane & 7;
    const int radd = (sub & 1) * 8;
    const int cadd = (sub >> 1) * 8;
#pragma unroll
    for (int ks = 0; ks < 8; ks++) {
        const int k0 = ks * 16;
        uint32_t a[2][4], bH[2][4], bL[2][4];
#pragma unroll
        for (int mt = 0; mt < 2; mt++) {
            uint32_t o = swz(wm * 32 + mt * 16 + l7 + radd, k0 + cadd);
            ldsm_x4(a[mt], sb + SM_A + o);
        }
#pragma unroll
        for (int pr = 0; pr < 2; pr++) {
            uint32_t o = swz(k0 + l7 + radd, wn * 32 + pr * 16 + cadd);
            ldsm_x4_t(bH[pr], sb + bHo + o);
            ldsm_x4_t(bL[pr], sb + bLo + o);
        }
#pragma unroll
        for (int mt = 0; mt < 2; mt++)
#pragma unroll
            for (int nt = 0; nt < 4; nt++) {
                const uint32_t* bh = &bH[nt >> 1][(nt & 1) * 2];
                const uint32_t* bl = &bL[nt >> 1][(nt & 1) * 2];
                mma16816(acc[mt][nt], a[mt], bh);
                mma16816(acc[mt][nt], a[mt], bl);
            }
    }
}

// ---------------- GEMM over z: by=0 -> z@Ws (fp16 table); by=1 -> z@Wz (fp32 P)
__global__ __launch_bounds__(NTHREADS)
void gemm_z(int M)
{
    extern __shared__ char smem[];
    const uint32_t sb = smem_u32(smem);
    const int tid = threadIdx.x;
    const int wid = tid >> 5;
    const int lane = tid & 31;
    const int tile = blockIdx.x;
    const int bm0 = tile * 128;
    const int by = blockIdx.y;

    copy_blobA(g_zA + (size_t)tile * 16384, smem, tid);
    copy_B(by, smem, SM_BHI, SM_BLO, tid);   // 0=Ws, 1=Wz
    __syncthreads();

    const int wm = wid & 3, wn = wid >> 2;
    float acc[2][4][4];
#pragma unroll
    for (int mt = 0; mt < 2; mt++)
#pragma unroll
        for (int nt = 0; nt < 4; nt++)
#pragma unroll
            for (int j = 0; j < 4; j++) acc[mt][nt][j] = 0.f;

    mma_stage(sb, SM_BHI, SM_BLO, wm, wn, lane, acc);

    const int g = lane >> 2, tg = lane & 3;
#pragma unroll
    for (int mt = 0; mt < 2; mt++)
#pragma unroll
        for (int half = 0; half < 2; half++) {
            int r = bm0 + wm * 32 + mt * 16 + g + half * 8;
            if (r >= M) continue;
#pragma unroll
            for (int nt = 0; nt < 4; nt++) {
                int lc = wn * 32 + nt * 8 + 2 * tg;
                float vx = acc[mt][nt][half * 2 + 0];
                float vy = acc[mt][nt][half * 2 + 1];
                if (by == 0) {
                    *(__half2*)(g_Ps16 + (size_t)r * HID + lc) = __floats2half2_rn(vx, vy);
                } else {
                    *(float2*)(g_P + (size_t)r * HID + lc) = make_float2(vx, vy);
                }
            }
        }
}

// ---------------- fused tail: out = relu(aggX@W1b + P + b1) @ W2 + b2 ----------------
__global__ __launch_bounds__(NTHREADS)
void gemm_tail(const float* __restrict__ b1, const float* __restrict__ b2,
               float* __restrict__ out, int M)
{
    extern __shared__ char smem[];
    const uint32_t sb = smem_u32(smem);
    const int tid = threadIdx.x;
    const int wid = tid >> 5;
    const int lane = tid & 31;
    const int tile = blockIdx.x;
    const int bm0 = tile * 128;
    const int wm = wid & 3, wn = wid >> 2;
    const int g = lane >> 2, tg = lane & 3;

    copy_blobA(g_aggA + (size_t)tile * 16384, smem, tid);
    copy_B(2, smem, SM_BHI, SM_BLO, tid);   // W1b
    copy_B(3, smem, SM_B2H, SM_B2L, tid);   // W2
    __syncthreads();

    float acc[2][4][4];
#pragma unroll
    for (int mt = 0; mt < 2; mt++)
#pragma unroll
        for (int nt = 0; nt < 4; nt++)
#pragma unroll
            for (int j = 0; j < 4; j++) acc[mt][nt][j] = 0.f;

    mma_stage(sb, SM_BHI, SM_BLO, wm, wn, lane, acc);
    __syncthreads();   // all reads of A smem done before overwrite

    // hidden = relu(acc + b1 + P) -> fp16 back into A smem
#pragma unroll
    for (int mt = 0; mt < 2; mt++)
#pragma unroll
        for (int half = 0; half < 2; half++) {
            int lr = wm * 32 + mt * 16 + g + half * 8;
            int r = bm0 + lr;
            const float* crow = (r < M) ? (g_P + (size_t)r * HID) : nullptr;
#pragma unroll
            for (int nt = 0; nt < 4; nt++) {
                int lc = wn * 32 + nt * 8 + 2 * tg;
                float vx = acc[mt][nt][half * 2 + 0] + b1[lc];
                float vy = acc[mt][nt][half * 2 + 1] + b1[lc + 1];
                if (crow) { vx += crow[lc]; vy += crow[lc + 1]; }
                vx = fmaxf(vx, 0.f); vy = fmaxf(vy, 0.f);
                uint32_t off = swz(lr, lc);
                *(uint32_t*)(smem + SM_A + off) = pack2h(vx, vy);
            }
        }
    __syncthreads();

#pragma unroll
    for (int mt = 0; mt < 2; mt++)
#pragma unroll
        for (int nt = 0; nt < 4; nt++)
#pragma unroll
            for (int j = 0; j < 4; j++) acc[mt][nt][j] = 0.f;

    mma_stage(sb, SM_B2H, SM_B2L, wm, wn, lane, acc);

#pragma unroll
    for (int mt = 0; mt < 2; mt++)
#pragma unroll
        for (int half = 0; half < 2; half++) {
            int r = bm0 + wm * 32 + mt * 16 + g + half * 8;
            if (r >= M) continue;
            float* orow = out + (size_t)r * HID;
#pragma unroll
            for (int nt = 0; nt < 4; nt++) {
                int lc = wn * 32 + nt * 8 + 2 * tg;
                float2 v;
                v.x = acc[mt][nt][half * 2 + 0] + b2[lc];
                v.y = acc[mt][nt][half * 2 + 1] + b2[lc + 1];
                *(float2*)(orow + lc) = v;
            }
        }
}

// ---------------- fused prep (cooperative) ----------------
__global__ void prep_kernel(const int* __restrict__ esrc, const int* __restrict__ edst,
                            const float* __restrict__ ew, const float* __restrict__ z,
                            const float* __restrict__ Wm, const float* __restrict__ W1,
                            const float* __restrict__ W2)
{
    cg::grid_group grid = cg::this_grid();
    const int bid = blockIdx.x, t = threadIdx.x;
    const int gt = bid * 256 + t;
    const int gsz = gridDim.x * 256;

    // weight splits (fp16 hi/lo): Ws -> slot0, W1b -> slot2, W2 -> slot3
    for (int idx = gt; idx < 3 * 16384; idx += gsz) {
        int m = idx >> 14;
        int p = idx & 16383;
        int row = p >> 7, col = p & 127;
        const float* src = (m == 0) ? (Wm + 128 * 128)
                         : (m == 1) ? (W1 + 128 * 128) : W2;
        int slot = (m == 0) ? 0 : (m == 1) ? 2 : 3;
        float v = src[row * 128 + col];
        float h = toh(v);
        uint32_t off = swz(row, col);
        *(__half*)((char*)g_WH[slot] + off) = __float2half_rn(h);
        *(__half*)((char*)g_WL[slot] + off) = __float2half_rn(v - h);
    }
    // Wz = W1a + Wd @ W1b  -> slot1
    for (int idx = gt; idx < 16384; idx += gsz) {
        int row = idx >> 7, col = idx & 127;
        float acc = W1[row * 128 + col];                 // W1a
        const float* wd = Wm + row * 128;                // Wd row
        const float* w1b = W1 + 128 * 128 + col;         // W1b col
#pragma unroll 8
        for (int k = 0; k < 128; k++) acc += wd[k] * w1b[k * 128];
        float h = toh(acc);
        uint32_t off = swz(row, col);
        *(__half*)((char*)g_WH[1] + off) = __float2half_rn(h);
        *(__half*)((char*)g_WL[1] + off) = __float2half_rn(acc - h);
    }
    // z -> fp16 swizzled per-tile blobs (pairs)
    for (int idx = gt; idx < NTILES * 8192; idx += gsz) {
        int tile = idx >> 13;
        int p = idx & 8191;
        int row = p >> 6, col = (p & 63) * 2;
        int gr = tile * 128 + row;
        float2 v = make_float2(0.f, 0.f);
        if (gr < N_NODES) v = *(const float2*)(z + (size_t)gr * 128 + col);
        uint32_t off = (uint32_t)tile * 32768u + swz(row, col);
        *(uint32_t*)((char*)g_zA + off) = pack2h(v.x, v.y);
    }
    // zero counts
    for (int i = gt; i < N_NODES; i += gsz) g_count[i] = 0;
    grid.sync();

    // histogram
    for (int i = gt; i < N_EDGES; i += gsz) atomicAdd(&g_count[edst[i]], 1);
    grid.sync();

    // block-local scan
    __shared__ int ws[8];
    if (bid < SCAN_BLOCKS) {
        int i = bid * 256 + t;
        int v = (i < N_NODES) ? g_count[i] : 0;
        int lane = t & 31, w = t >> 5;
        int incl = v;
#pragma unroll
        for (int o = 1; o < 32; o <<= 1) {
            int y = __shfl_up_sync(0xffffffffu, incl, o);
            if (lane >= o) incl += y;
        }
        if (lane == 31) ws[w] = incl;
        __syncthreads();
        if (t < 8) {
            int x = ws[t];
#pragma unroll
            for (int o = 1; o < 8; o <<= 1) {
                int y = __shfl_up_sync(0xffu, x, o, 8);
                if (t >= o) x += y;
            }
            ws[t] = x;
        }
        __syncthreads();
        int excl = incl - v + (w > 0 ? ws[w - 1] : 0);
        if (i < N_NODES) g_offset[i] = excl;
        if (t == 255) g_blocksum[bid] = ws[7];
    }
    grid.sync();

    // scan block sums
    if (bid == 0) {
        int v = (t < SCAN_BLOCKS) ? g_blocksum[t] : 0;
        int lane = t & 31, w = t >> 5;
        int incl = v;
#pragma unroll
        for (int o = 1; o < 32; o <<= 1) {
            int y = __shfl_up_sync(0xffffffffu, incl, o);
            if (lane >= o) incl += y;
        }
        if (lane == 31) ws[w] = incl;
        __syncthreads();
        if (t < 8) {
            int x = ws[t];
#pragma unroll
            for (int o = 1; o < 8; o <<= 1) {
                int y = __shfl_up_sync(0xffu, x, o, 8);
                if (t >= o) x += y;
            }
            ws[t] = x;
        }
        __syncthreads();
        int excl = incl - v + (w > 0 ? ws[w - 1] : 0);
        if (t < SCAN_BLOCKS) g_blocksum[t] = excl;
    }
    grid.sync();

    // add block offsets, init cursor
    if (bid < SCAN_BLOCKS) {
        int i = bid * 256 + t;
        if (i < N_NODES) {
            int off = g_offset[i] + g_blocksum[bid];
            g_offset[i] = off;
            g_cursor[i] = off;
        }
    }
    grid.sync();

    // scatter
    for (int i = gt; i < N_EDGES; i += gsz) {
        int d = edst[i];
        int pos = atomicAdd(&g_cursor[d], 1);
        g_sorted[pos] = make_int2(esrc[i], __float_as_int(ew[i]));
    }
}

// ---------------- aggregation: writes (bm + mx) as fp16 swizzled blobs ----------------
// deg==0 node: row = -(z@Wd) so that row@W1b cancels the folded q@W1b term.
__global__ void agg_kernel(const float* __restrict__ Wm, const float* __restrict__ bm,
                           const float* __restrict__ z) {
    int gw = (blockIdx.x * blockDim.x + threadIdx.x) >> 5;
    int lane = threadIdx.x & 31;
    const int NPAD = NTILES * 128;   // 50048
    if (gw >= NPAD) return;

    float4 outv = make_float4(0.f, 0.f, 0.f, 0.f);
    if (gw < N_NODES) {
        int start = g_offset[gw];
        int end = (gw + 1 < N_NODES ? g_offset[gw + 1] : N_EDGES);
        if (end > start) {
            float4 w4 = *(const float4*)(Wm + 256 * 128 + lane * 4);  // ww
            const float NI = -CUDART_INF_F;
            float4 m0 = make_float4(NI, NI, NI, NI);
            float4 m1 = make_float4(NI, NI, NI, NI);
            int e = start;
            for (; e + 2 <= end; e += 2) {
                int2 p0 = __ldg(&g_sorted[e]);
                int2 p1 = __ldg(&g_sorted[e + 1]);
                uint2 u0 = *(const uint2*)(g_Ps16 + (size_t)p0.x * HID + lane * 4);
                uint2 u1 = *(const uint2*)(g_Ps16 + (size_t)p1.x * HID + lane * 4);
                float w0 = __int_as_float(p0.y);
                float w1 = __int_as_float(p1.y);
                float2 a01 = __half22float2(*(__half2*)&u0.x);
                float2 a23 = __half22float2(*(__half2*)&u0.y);
                float2 b01 = __half22float2(*(__half2*)&u1.x);
                float2 b23 = __half22float2(*(__half2*)&u1.y);
                m0.x = fmaxf(m0.x, fmaf(w0, w4.x, a01.x));
                m0.y = fmaxf(m0.y, fmaf(w0, w4.y, a01.y));
                m0.z = fmaxf(m0.z, fmaf(w0, w4.z, a23.x));
                m0.w = fmaxf(m0.w, fmaf(w0, w4.w, a23.y));
                m1.x = fmaxf(m1.x, fmaf(w1, w4.x, b01.x));
                m1.y = fmaxf(m1.y, fmaf(w1, w4.y, b01.y));
                m1.z = fmaxf(m1.z, fmaf(w1, w4.z, b23.x));
                m1.w = fmaxf(m1.w, fmaf(w1, w4.w, b23.y));
            }
            if (e < end) {
                int2 p0 = __ldg(&g_sorted[e]);
                uint2 u0 = *(const uint2*)(g_Ps16 + (size_t)p0.x * HID + lane * 4);
                float w0 = __int_as_float(p0.y);
                float2 a01 = __half22float2(*(__half2*)&u0.x);
                float2 a23 = __half22float2(*(__half2*)&u0.y);
                m0.x = fmaxf(m0.x, fmaf(w0, w4.x, a01.x));
                m0.y = fmaxf(m0.y, fmaf(w0, w4.y, a01.y));
                m0.z = fmaxf(m0.z, fmaf(w0, w4.z, a23.x));
                m0.w = fmaxf(m0.w, fmaf(w0, w4.w, a23.y));
            }
            m0.x = fmaxf(m0.x, m1.x); m0.y = fmaxf(m0.y, m1.y);
            m0.z = fmaxf(m0.z, m1.z); m0.w = fmaxf(m0.w, m1.w);

            float4 b = *(const float4*)(bm + lane * 4);
            outv.x = b.x + m0.x;
            outv.y = b.y + m0.y;
            outv.z = b.z + m0.z;
            outv.w = b.w + m0.w;
        } else {
            // deg==0: outv = -(z[gw] @ Wd)[4*lane .. 4*lane+3]
            const float* zr = z + (size_t)gw * 128;
            float s0 = 0.f, s1 = 0.f, s2 = 0.f, s3 = 0.f;
            for (int k = 0; k < 128; k++) {
                float zv = zr[k];
                const float* wd = Wm + k * 128 + lane * 4;
                s0 = fmaf(zv, wd[0], s0);
                s1 = fmaf(zv, wd[1], s1);
                s2 = fmaf(zv, wd[2], s2);
                s3 = fmaf(zv, wd[3], s3);
            }
            outv = make_float4(-s0, -s1, -s2, -s3);
        }
    }
    // write fp16 into swizzled tile blob (4 halfs = 8B, within one 16B chunk)
    int tile = gw >> 7, row = gw & 127, col = lane * 4;
    uint32_t off = (uint32_t)tile * 32768u + swz(row, col);
    uint2 hv = make_uint2(pack2h(outv.x, outv.y), pack2h(outv.z, outv.w));
    *(uint2*)((char*)g_aggA + off) = hv;
}

// ---------------- launch ----------------
extern "C" void kernel_launch(void* const* d_in, const int* in_sizes, int n_in,
                              void* d_out, int out_size) {
    const float* z    = (const float*)d_in[0];
    const float* ew   = (const float*)d_in[1];
    const int*   esrc = (const int*)d_in[2];
    const int*   edst = (const int*)d_in[3];
    const float* Wm   = (const float*)d_in[4];
    const float* bm   = (const float*)d_in[5];
    const float* W1   = (const float*)d_in[6];
    const float* b1   = (const float*)d_in[7];
    const float* W2   = (const float*)d_in[8];
    const float* b2   = (const float*)d_in[9];
    float* out = (float*)d_out;

    static int prep_blocks = 0;
    static bool init_done = false;
    if (!init_done) {
        cudaFuncSetAttribute(gemm_z,    cudaFuncAttributeMaxDynamicSharedMemorySize, SM_TOTAL);
        cudaFuncSetAttribute(gemm_tail, cudaFuncAttributeMaxDynamicSharedMemorySize, SM_T_TOTAL);
        int nb = 0, nsm = 0;
        cudaOccupancyMaxActiveBlocksPerMultiprocessor(&nb, prep_kernel, 256, 0);
        cudaDeviceGetAttribute(&nsm, cudaDevAttrMultiProcessorCount, 0);
        prep_blocks = nb * nsm;
        if (prep_blocks < SCAN_BLOCKS) prep_blocks = SCAN_BLOCKS;
        init_done = true;
    }

    // 1. fused prep: weight splits + Wz + z fp16 blobs + edge counting sort (cooperative)
    {
        void* args[7] = { (void*)&esrc, (void*)&edst, (void*)&ew, (void*)&z,
                          (void*)&Wm, (void*)&W1, (void*)&W2 };
        cudaLaunchCooperativeKernel((void*)prep_kernel, dim3(prep_blocks), dim3(256), args, 0, 0);
    }

    // 2. z GEMMs: by0 -> fp16 z@Ws table; by1 -> z@Wz (fp32 P)
    gemm_z<<<dim3(NTILES, 2), NTHREADS, SM_TOTAL>>>(N_NODES);

    // 3. aggregation -> fp16 swizzled blobs
    agg_kernel<<<(NTILES * 128 * 32) / 256, 256>>>(Wm, bm, z);

    // 4. fused tail: out = relu(aggX@W1b + P + b1) @ W2 + b2
    gemm_tail<<<NTILES, NTHREADS, SM_T_TOTAL>>>(b1, b2, out, N_NODES);
}